// round 12
// baseline (speedup 1.0000x reference)
#include <cuda_runtime.h>
#include <cuda_bf16.h>
#include <math.h>
#include <stdint.h>

#define T_STEPS 128
#define BATCH   256
#define DIN     256
#define DH      1024
#define DOUT    256

// ---------------- device scratch ----------------
__device__ float g_hf[(size_t)BATCH * DH];                   // fp32 h (final step only)
__device__ __nv_bfloat16 g_h_hi[2][(size_t)BATCH * DH];      // ping-pong split h
__device__ __nv_bfloat16 g_h_lo[2][(size_t)BATCH * DH];
__device__ __nv_bfloat16 g_wt_hi[(size_t)DH * DH];           // W1h^T split: wt[n][k]
__device__ __nv_bfloat16 g_wt_lo[(size_t)DH * DH];
__device__ __nv_bfloat16 g_xs_hi[(size_t)T_STEPS * BATCH * DIN];  // xs split
__device__ __nv_bfloat16 g_xs_lo[(size_t)T_STEPS * BATCH * DIN];
__device__ __nv_bfloat16 g_w1xt_hi[(size_t)DH * DIN];        // W1x^T split [n][k]
__device__ __nv_bfloat16 g_w1xt_lo[(size_t)DH * DIN];
// per-(step, m-group) barrier slots, each padded to 128B (own L2 line)
__device__ int g_bar[T_STEPS * 4 * 32];

// ---------------- helpers ----------------
__device__ __forceinline__ uint32_t smem_u32(const void* p) {
    uint32_t a;
    asm("{ .reg .u64 t; cvta.to.shared.u64 t, %1; cvt.u32.u64 %0, t; }" : "=r"(a) : "l"(p));
    return a;
}
__device__ __forceinline__ void cp_async16(uint32_t dst, const void* src) {
    asm volatile("cp.async.cg.shared.global [%0], [%1], 16;" :: "r"(dst), "l"(src) : "memory");
}
__device__ __forceinline__ void cp_commit() {
    asm volatile("cp.async.commit_group;" ::: "memory");
}
__device__ __forceinline__ void cp_wait0() {
    asm volatile("cp.async.wait_group 0;" ::: "memory");
}
__device__ __forceinline__ void cp_wait1() {
    asm volatile("cp.async.wait_group 1;" ::: "memory");
}
__device__ __forceinline__ void ldmatrix_x4(uint32_t* r, uint32_t addr) {
    asm volatile("ldmatrix.sync.aligned.m8n8.x4.shared.b16 {%0,%1,%2,%3}, [%4];"
                 : "=r"(r[0]), "=r"(r[1]), "=r"(r[2]), "=r"(r[3]) : "r"(addr));
}
__device__ __forceinline__ void mma_bf16(float* c, const uint32_t* a,
                                         uint32_t b0, uint32_t b1) {
    asm volatile(
        "mma.sync.aligned.m16n8k16.row.col.f32.bf16.bf16.f32 "
        "{%0,%1,%2,%3},{%4,%5,%6,%7},{%8,%9},{%0,%1,%2,%3};"
        : "+f"(c[0]), "+f"(c[1]), "+f"(c[2]), "+f"(c[3])
        : "r"(a[0]), "r"(a[1]), "r"(a[2]), "r"(a[3]), "r"(b0), "r"(b1));
}
__device__ __forceinline__ float tanh_fast(float x) {
    float ax = fabsf(x);
    float e;
    asm("ex2.approx.f32 %0, %1;" : "=f"(e) : "f"(ax * -2.885390081777927f)); // e^{-2|x|}
    float r = __fdividef(1.0f - e, 1.0f + e);
    return __uint_as_float(__float_as_uint(r) | (__float_as_uint(x) & 0x80000000u));
}
__device__ __forceinline__ uint32_t prmt_hi(uint32_t x, uint32_t y) {
    uint32_t d;
    asm("prmt.b32 %0, %1, %2, 0x7632;" : "=r"(d) : "r"(x), "r"(y));
    return d;
}
__device__ __forceinline__ uint32_t cvt_bf16x2(float hi, float lo) {
    uint32_t d;
    asm("cvt.rn.bf16x2.f32 %0, %1, %2;" : "=r"(d) : "f"(hi), "f"(lo));
    return d;
}

// ---------------- utility kernels ----------------
__global__ void zero_u4(uint4* __restrict__ p, int n4) {
    int i = blockIdx.x * blockDim.x + threadIdx.x;
    if (i < n4) p[i] = make_uint4(0, 0, 0, 0);
}

__global__ void fsplit_kernel(const float* __restrict__ in,
                              __nv_bfloat16* __restrict__ hi,
                              __nv_bfloat16* __restrict__ lo, int n4) {
    int i = blockIdx.x * blockDim.x + threadIdx.x;
    if (i >= n4) return;
    float4 v = reinterpret_cast<const float4*>(in)[i];
    uint32_t u0 = __float_as_uint(v.x), u1 = __float_as_uint(v.y);
    uint32_t u2 = __float_as_uint(v.z), u3 = __float_as_uint(v.w);
    reinterpret_cast<uint2*>(hi)[i] = make_uint2(prmt_hi(u0, u1), prmt_hi(u2, u3));
    float l0 = v.x - __uint_as_float(u0 & 0xFFFF0000u);
    float l1 = v.y - __uint_as_float(u1 & 0xFFFF0000u);
    float l2 = v.z - __uint_as_float(u2 & 0xFFFF0000u);
    float l3 = v.w - __uint_as_float(u3 & 0xFFFF0000u);
    reinterpret_cast<uint2*>(lo)[i] = make_uint2(cvt_bf16x2(l1, l0), cvt_bf16x2(l3, l2));
}

// transpose + bf16 split: W[k][n] (KxN) -> out[n][k]
__global__ void wsplit_kernel(const float* __restrict__ W,
                              __nv_bfloat16* __restrict__ hi,
                              __nv_bfloat16* __restrict__ lo, int K, int N) {
    __shared__ float t[32][33];
    const int tx = threadIdx.x, ty = threadIdx.y;
    const int kb = blockIdx.y * 32, nb = blockIdx.x * 32;
#pragma unroll
    for (int i = 0; i < 32; i += 8)
        t[ty + i][tx] = W[(size_t)(kb + ty + i) * N + nb + tx];
    __syncthreads();
#pragma unroll
    for (int i = 0; i < 32; i += 8) {
        const int n = nb + ty + i, k = kb + tx;
        float v = t[tx][ty + i];
        __nv_bfloat16 h = __float2bfloat16(v);
        hi[(size_t)n * K + k] = h;
        lo[(size_t)n * K + k] = __float2bfloat16(v - __bfloat162float(h));
    }
}

// =====================================================================
// Persistent fused recurrence: h <- tanh(x_t@W1x + h@W1h + b1).
// grid 128 CTAs x 256 threads; CTA c: n0=(c&31)*32, m0=(c>>5)*64.
// smem: W1h^T slice hi/lo (128KB) + W1x^T slice hi/lo (32KB) resident;
// 2 A-stages (32KB each). Per step: 2 x-tiles (K=256) + 8 h-tiles
// (K=1024), 8 warps split-K over k16 slices, 3-term bf16 accumulate.
// Two-phase split-K reduction (32-row halves) reusing the stage region.
// Step 0: x-tiles only (h(-1)=0). Per-m-group barrier between steps.
// =====================================================================
#define W_HI_OFF  0
#define W_LO_OFF  65536
#define WX_HI_OFF 131072
#define WX_LO_OFF 147456
#define ST_OFF    163840
#define ST_SZ     32768
#define SMEM_TOT  229376
#define RP 36

__global__ void __launch_bounds__(256, 1)
rnn_persist(const __nv_bfloat16* __restrict__ hhi0, const __nv_bfloat16* __restrict__ hlo0,
            const __nv_bfloat16* __restrict__ wt_hi, const __nv_bfloat16* __restrict__ wt_lo,
            const __nv_bfloat16* __restrict__ wx_hi, const __nv_bfloat16* __restrict__ wx_lo,
            const __nv_bfloat16* __restrict__ xs_hi, const __nv_bfloat16* __restrict__ xs_lo,
            const float* __restrict__ b1, float* __restrict__ o_f,
            int* __restrict__ bar) {
    extern __shared__ __align__(128) char sm[];
    const uint32_t sb = smem_u32(sm);

    const int tid = threadIdx.x;
    const int w = tid >> 5;
    const int lane = tid & 31;
    const int cta = blockIdx.x;
    const int n0 = (cta & 31) * 32;
    const int m0 = (cta >> 5) * 64;
    const int mg = cta >> 5;
    const size_t HS = (size_t)BATCH * DH;

    // ---- load resident weights into smem once ----
    {
#pragma unroll
        for (int i = 0; i < 16; i++) {              // W1h hi: 32 rows x 2048B
            const int c = tid + i * 256;
            const int row = c >> 7, u = c & 127;
            cp_async16(sb + W_HI_OFF + row * 2048 + ((u * 16) ^ ((row & 7) << 4)),
                       wt_hi + (size_t)(n0 + row) * DH + u * 8);
        }
#pragma unroll
        for (int i = 0; i < 16; i++) {              // W1h lo
            const int c = tid + i * 256;
            const int row = c >> 7, u = c & 127;
            cp_async16(sb + W_LO_OFF + row * 2048 + ((u * 16) ^ ((row & 7) << 4)),
                       wt_lo + (size_t)(n0 + row) * DH + u * 8);
        }
#pragma unroll
        for (int i = 0; i < 4; i++) {               // W1x hi: 32 rows x 512B
            const int c = tid + i * 256;
            const int row = c >> 5, u = c & 31;
            cp_async16(sb + WX_HI_OFF + row * 512 + ((u * 16) ^ ((row & 7) << 4)),
                       wx_hi + (size_t)(n0 + row) * DIN + u * 8);
        }
#pragma unroll
        for (int i = 0; i < 4; i++) {               // W1x lo
            const int c = tid + i * 256;
            const int row = c >> 5, u = c & 31;
            cp_async16(sb + WX_LO_OFF + row * 512 + ((u * 16) ^ ((row & 7) << 4)),
                       wx_lo + (size_t)(n0 + row) * DIN + u * 8);
        }
        cp_commit();
    }

    // consumer addressing (constant across steps)
    const int l7 = lane & 7;
    const uint32_t xmk = (uint32_t)(l7 << 4);
    const int rowA = ((lane >> 3) & 1) * 8 + l7;
    const uint32_t kselA = ((lane >> 4) & 1) * 16;
    const int rowBb = ((lane >> 4) & 1) * 8 + l7;
    const uint32_t kselB = ((lane >> 3) & 1) * 16;
    const uint32_t wkb = (uint32_t)(w * 32);

    // epilogue addressing (constant)
    const int prow = tid >> 3;          // 0..31 within phase
    const int pcol = (tid & 7) * 4;     // 0..28
    const float4 b1v = *reinterpret_cast<const float4*>(b1 + n0 + pcol);

    for (int t = 0; t < T_STEPS; t++) {
        const int cur = t & 1;
        const __nv_bfloat16* h_hi = hhi0 + cur * HS;
        const __nv_bfloat16* h_lo = hlo0 + cur * HS;
        __nv_bfloat16* o_hi = const_cast<__nv_bfloat16*>(hhi0) + (cur ^ 1) * HS;
        __nv_bfloat16* o_lo = const_cast<__nv_bfloat16*>(hlo0) + (cur ^ 1) * HS;
        const __nv_bfloat16* x_hi = xs_hi + (size_t)t * BATCH * DIN;
        const __nv_bfloat16* x_lo = xs_lo + (size_t)t * BATCH * DIN;
        const int ntiles = (t == 0) ? 2 : 10;       // tiles 0,1 = x; 2..9 = h

        auto issue = [&](int kt, int buf) {
            const uint32_t st = sb + ST_OFF + buf * ST_SZ;
            if (kt < 2) {
                const int k0 = kt << 7;
#pragma unroll
                for (int i = 0; i < 4; i++) {       // x_hi: 64 rows x 256B
                    const int c = tid + (i << 8);
                    const int row = c >> 4, u = c & 15;
                    cp_async16(st + row * 256 + ((u * 16) ^ ((row & 7) << 4)),
                               x_hi + (size_t)(m0 + row) * DIN + k0 + u * 8);
                }
#pragma unroll
                for (int i = 0; i < 4; i++) {       // x_lo
                    const int c = tid + (i << 8);
                    const int row = c >> 4, u = c & 15;
                    cp_async16(st + 16384 + row * 256 + ((u * 16) ^ ((row & 7) << 4)),
                               x_lo + (size_t)(m0 + row) * DIN + k0 + u * 8);
                }
            } else {
                const int k0 = (kt - 2) << 7;
#pragma unroll
                for (int i = 0; i < 4; i++) {       // h_hi: 64 rows x 256B
                    const int c = tid + (i << 8);
                    const int row = c >> 4, u = c & 15;
                    cp_async16(st + row * 256 + ((u * 16) ^ ((row & 7) << 4)),
                               h_hi + (size_t)(m0 + row) * DH + k0 + u * 8);
                }
#pragma unroll
                for (int i = 0; i < 4; i++) {       // h_lo
                    const int c = tid + (i << 8);
                    const int row = c >> 4, u = c & 15;
                    cp_async16(st + 16384 + row * 256 + ((u * 16) ^ ((row & 7) << 4)),
                               h_lo + (size_t)(m0 + row) * DH + k0 + u * 8);
                }
            }
        };

        float acc[4][4][4];
#pragma unroll
        for (int mt = 0; mt < 4; mt++)
#pragma unroll
            for (int n8 = 0; n8 < 4; n8++)
#pragma unroll
                for (int q = 0; q < 4; q++) acc[mt][n8][q] = 0.0f;

        auto compute = [&](int kt, int buf) {
            const uint32_t aHi = sb + ST_OFF + buf * ST_SZ;
            const uint32_t aLo = aHi + 16384;
            uint32_t bHiBase, bLoBase, pitch, tkb;
            if (kt < 2) {
                bHiBase = sb + WX_HI_OFF; bLoBase = sb + WX_LO_OFF;
                pitch = 512; tkb = (uint32_t)(kt << 8);
            } else {
                bHiBase = sb + W_HI_OFF;  bLoBase = sb + W_LO_OFF;
                pitch = 2048; tkb = (uint32_t)((kt - 2) << 8);
            }
            uint32_t ah[4][4], al[4][4], bh[2][4], bl[2][4];
#pragma unroll
            for (int mt = 0; mt < 4; mt++) {
                ldmatrix_x4(ah[mt], aHi + (mt * 16 + rowA) * 256 + ((wkb + kselA) ^ xmk));
                ldmatrix_x4(al[mt], aLo + (mt * 16 + rowA) * 256 + ((wkb + kselA) ^ xmk));
            }
#pragma unroll
            for (int nt = 0; nt < 2; nt++) {
                ldmatrix_x4(bh[nt], bHiBase + (nt * 16 + rowBb) * pitch +
                                        ((tkb + wkb + kselB) ^ xmk));
                ldmatrix_x4(bl[nt], bLoBase + (nt * 16 + rowBb) * pitch +
                                        ((tkb + wkb + kselB) ^ xmk));
            }
#pragma unroll
            for (int mt = 0; mt < 4; mt++)
#pragma unroll
                for (int nt = 0; nt < 2; nt++) {
                    mma_bf16(acc[mt][nt * 2],     ah[mt], bh[nt][0], bh[nt][1]);
                    mma_bf16(acc[mt][nt * 2 + 1], ah[mt], bh[nt][2], bh[nt][3]);
                    mma_bf16(acc[mt][nt * 2],     al[mt], bh[nt][0], bh[nt][1]);
                    mma_bf16(acc[mt][nt * 2 + 1], al[mt], bh[nt][2], bh[nt][3]);
                    mma_bf16(acc[mt][nt * 2],     ah[mt], bl[nt][0], bl[nt][1]);
                    mma_bf16(acc[mt][nt * 2 + 1], ah[mt], bl[nt][2], bl[nt][3]);
                }
        };

        // ---- pipelined mainloop (2 stages, depth-1 prefetch) ----
        issue(0, 0); cp_commit();
        for (int kt = 0; kt < ntiles; kt++) {
            cp_wait0();
            __syncthreads();
            if (kt + 1 < ntiles) { issue(kt + 1, (kt + 1) & 1); cp_commit(); }
            compute(kt, kt & 1);
        }
        __syncthreads();   // stage region now reused for reduction

        // ---- two-phase split-K reduction + fused epilogue ----
        float* sred = reinterpret_cast<float*>(sm + ST_OFF);
        const int g = lane >> 2, t4 = lane & 3;
#pragma unroll
        for (int p = 0; p < 2; p++) {
            float* ms = sred + w * (32 * RP);
#pragma unroll
            for (int mt2 = 0; mt2 < 2; mt2++) {
                const int mt = 2 * p + mt2;
#pragma unroll
                for (int n8 = 0; n8 < 4; n8++) {
                    const int r0 = mt2 * 16 + g, c = n8 * 8 + 2 * t4;
                    *reinterpret_cast<float2*>(&ms[r0 * RP + c]) =
                        make_float2(acc[mt][n8][0], acc[mt][n8][1]);
                    *reinterpret_cast<float2*>(&ms[(r0 + 8) * RP + c]) =
                        make_float2(acc[mt][n8][2], acc[mt][n8][3]);
                }
            }
            __syncthreads();
            {
                float4 s = *reinterpret_cast<const float4*>(&sred[prow * RP + pcol]);
#pragma unroll
                for (int w2 = 1; w2 < 8; w2++) {
                    float4 q = *reinterpret_cast<const float4*>(
                        &sred[w2 * (32 * RP) + prow * RP + pcol]);
                    s.x += q.x; s.y += q.y; s.z += q.z; s.w += q.w;
                }
                const size_t off = (size_t)(m0 + p * 32 + prow) * DH + n0 + pcol;
                float v0 = tanh_fast(s.x + b1v.x);
                float v1 = tanh_fast(s.y + b1v.y);
                float v2 = tanh_fast(s.z + b1v.z);
                float v3 = tanh_fast(s.w + b1v.w);
                if (t == T_STEPS - 1)
                    *reinterpret_cast<float4*>(o_f + off) = make_float4(v0, v1, v2, v3);
                uint32_t u0 = __float_as_uint(v0), u1 = __float_as_uint(v1);
                uint32_t u2 = __float_as_uint(v2), u3 = __float_as_uint(v3);
                *reinterpret_cast<uint2*>(o_hi + off) =
                    make_uint2(prmt_hi(u0, u1), prmt_hi(u2, u3));
                float l0 = v0 - __uint_as_float(u0 & 0xFFFF0000u);
                float l1 = v1 - __uint_as_float(u1 & 0xFFFF0000u);
                float l2 = v2 - __uint_as_float(u2 & 0xFFFF0000u);
                float l3 = v3 - __uint_as_float(u3 & 0xFFFF0000u);
                *reinterpret_cast<uint2*>(o_lo + off) =
                    make_uint2(cvt_bf16x2(l1, l0), cvt_bf16x2(l3, l2));
            }
            __syncthreads();
        }

        // ---- per-m-group barrier (32 arrivals; skip after last step) ----
        if (t < T_STEPS - 1) {
            if (tid == 0) {
                int* slot = bar + (t * 4 + mg) * 32;
                asm volatile("red.release.gpu.global.add.s32 [%0], 1;" :: "l"(slot) : "memory");
                int v;
                do {
                    __nanosleep(32);
                    asm volatile("ld.acquire.gpu.global.b32 %0, [%1];" : "=r"(v) : "l"(slot) : "memory");
                } while (v < 32);
            }
            __syncthreads();
        }
    }
}

// ---------------- packed f32x2 GEMM (readout only) ----------------
__device__ __forceinline__ void fma2(unsigned long long& acc,
                                     unsigned long long a, unsigned long long b) {
    asm("fma.rn.f32x2 %0, %1, %2, %0;" : "+l"(acc) : "l"(a), "l"(b));
}
__device__ __forceinline__ unsigned long long pack2(float x, float y) {
    unsigned long long r;
    asm("mov.b64 %0, {%1, %2};" : "=l"(r) : "f"(x), "f"(y));
    return r;
}
__device__ __forceinline__ float2 unpack2(unsigned long long v) {
    float2 f;
    asm("mov.b64 {%0, %1}, %2;" : "=f"(f.x), "=f"(f.y) : "l"(v));
    return f;
}

template <int BM, int BN, int BK, int TM>
__global__ void __launch_bounds__(256)
gemm_f32x2(const float* __restrict__ A, const float* __restrict__ Bm,
           const float* __restrict__ aux, float* __restrict__ C,
           int M, int N, int K) {
    constexpr int TN = 4;
    constexpr int NT = (BM / TM) * (BN / TN);
    static_assert(NT == 256, "block must be 256 threads");
    __shared__ float As[BK][BM + 4];
    __shared__ float Bs[BK][BN];

    const int tid = threadIdx.x;
    const int n0 = blockIdx.x * BN;
    const int m0 = blockIdx.y * BM;
    constexpr int A_PER = (BM * BK / 4) / NT;
    constexpr int B_PER = (BK * BN / 4) / NT;
    float4 ar[A_PER], br[B_PER];

    auto loadA = [&](int kt) {
#pragma unroll
        for (int i = 0; i < A_PER; i++) {
            int idx = tid + i * NT, row = idx / (BK / 4), kc = idx % (BK / 4);
            ar[i] = *reinterpret_cast<const float4*>(&A[(size_t)(m0 + row) * K + kt * BK + kc * 4]);
        }
    };
    auto storeA = [&]() {
#pragma unroll
        for (int i = 0; i < A_PER; i++) {
            int idx = tid + i * NT, row = idx / (BK / 4), kc = idx % (BK / 4);
            As[kc * 4 + 0][row] = ar[i].x; As[kc * 4 + 1][row] = ar[i].y;
            As[kc * 4 + 2][row] = ar[i].z; As[kc * 4 + 3][row] = ar[i].w;
        }
    };
    auto loadB = [&](int kt) {
#pragma unroll
        for (int i = 0; i < B_PER; i++) {
            int idx = tid + i * NT, kr = idx / (BN / 4), nc = idx % (BN / 4);
            br[i] = *reinterpret_cast<const float4*>(&Bm[(size_t)(kt * BK + kr) * N + n0 + nc * 4]);
        }
    };
    auto storeB = [&]() {
#pragma unroll
        for (int i = 0; i < B_PER; i++) {
            int idx = tid + i * NT, kr = idx / (BN / 4), nc = idx % (BN / 4);
            *reinterpret_cast<float4*>(&Bs[kr][nc * 4]) = br[i];
        }
    };

    unsigned long long acc[TM][2];
#pragma unroll
    for (int i = 0; i < TM; i++) { acc[i][0] = pack2(0, 0); acc[i][1] = pack2(0, 0); }

    const int rg = tid / (BN / TN), cg = tid % (BN / TN);
    const int r0 = rg * TM, c0 = cg * TN;
    const int nk = K / BK;
    loadA(0); loadB(0); storeA(); storeB();
    __syncthreads();
    for (int kt = 0; kt < nk; kt++) {
        if (kt + 1 < nk) { loadA(kt + 1); loadB(kt + 1); }
#pragma unroll
        for (int k = 0; k < BK; k++) {
            float a[TM];
            if (TM == 2) {
                float2 avv = *reinterpret_cast<const float2*>(&As[k][r0]);
                a[0] = avv.x; a[1] = avv.y;
            } else {
                float4 avv = *reinterpret_cast<const float4*>(&As[k][r0]);
                a[0] = avv.x; a[1] = avv.y; a[2] = avv.z; a[3] = avv.w;
            }
            float4 bvv = *reinterpret_cast<const float4*>(&Bs[k][c0]);
            unsigned long long b01 = pack2(bvv.x, bvv.y), b23 = pack2(bvv.z, bvv.w);
#pragma unroll
            for (int i = 0; i < TM; i++) {
                unsigned long long aa = pack2(a[i], a[i]);
                fma2(acc[i][0], aa, b01);
                fma2(acc[i][1], aa, b23);
            }
        }
        __syncthreads();
        if (kt + 1 < nk) { storeA(); storeB(); __syncthreads(); }
    }
#pragma unroll
    for (int i = 0; i < TM; i++) {
        float2 p0 = unpack2(acc[i][0]), p1 = unpack2(acc[i][1]);
        float4 v = make_float4(p0.x, p0.y, p1.x, p1.y);
        const int row = m0 + r0 + i, col = n0 + c0;
        const size_t off = (size_t)row * N + col;
        float s = aux[0];
        v.x += s; v.y += s; v.z += s; v.w += s;
        *reinterpret_cast<float4*>(&C[off]) = v;
    }
}

// ---------------- host launcher ----------------
extern "C" void kernel_launch(void* const* d_in, const int* in_sizes, int n_in,
                              void* d_out, int out_size) {
    const float* xs  = (const float*)d_in[0];
    const float* W1x = (const float*)d_in[1];
    const float* W1h = (const float*)d_in[2];
    const float* b1  = (const float*)d_in[3];
    const float* W2  = (const float*)d_in[4];
    const float* b2  = (const float*)d_in[5];
    float* out = (float*)d_out;

    float* hf;
    int* barp;
    __nv_bfloat16 *hhi, *hlo, *wthi, *wtlo, *xshi, *xslo, *wxhi, *wxlo;
    cudaGetSymbolAddress((void**)&hf, g_hf);
    cudaGetSymbolAddress((void**)&hhi, g_h_hi);
    cudaGetSymbolAddress((void**)&hlo, g_h_lo);
    cudaGetSymbolAddress((void**)&wthi, g_wt_hi);
    cudaGetSymbolAddress((void**)&wtlo, g_wt_lo);
    cudaGetSymbolAddress((void**)&xshi, g_xs_hi);
    cudaGetSymbolAddress((void**)&xslo, g_xs_lo);
    cudaGetSymbolAddress((void**)&wxhi, g_w1xt_hi);
    cudaGetSymbolAddress((void**)&wxlo, g_w1xt_lo);
    cudaGetSymbolAddress((void**)&barp, g_bar);

    cudaFuncSetAttribute(rnn_persist, cudaFuncAttributeMaxDynamicSharedMemorySize, SMEM_TOT);

    const int XN = T_STEPS * BATCH * DIN;

    // splits
    fsplit_kernel<<<XN / 4 / 256, 256>>>(xs, xshi, xslo, XN / 4);
    wsplit_kernel<<<dim3(DH / 32, DIN / 32), dim3(32, 8)>>>(W1x, wxhi, wxlo, DIN, DH);
    wsplit_kernel<<<dim3(DH / 32, DH / 32), dim3(32, 8)>>>(W1h, wthi, wtlo, DH, DH);

    // zero barrier slots
    zero_u4<<<16, 256>>>((uint4*)barp, T_STEPS * 4 * 32 / 4);

    // fused recurrence: z + h@W1h + tanh, all 128 steps, one launch
    rnn_persist<<<128, 256, SMEM_TOT>>>(hhi, hlo, wthi, wtlo, wxhi, wxlo,
                                        xshi, xslo, b1, hf, barp);

    // out = h_final @ W2 + b2
    gemm_f32x2<32, 64, 32, 2>
        <<<dim3(DOUT / 64, BATCH / 32), 256>>>(hf, W2, b2, out, BATCH, DOUT, DH);
}

// round 13
// speedup vs baseline: 1.2187x; 1.2187x over previous
#include <cuda_runtime.h>
#include <cuda_bf16.h>
#include <math.h>
#include <stdint.h>

#define T_STEPS 128
#define BATCH   256
#define DIN     256
#define DH      1024
#define DOUT    256

// ---------------- device scratch ----------------
__device__ float g_z[(size_t)T_STEPS * BATCH * DH];          // 134 MB: xs@W1x + b1
__device__ float g_hf[(size_t)BATCH * DH];                   // fp32 h (final step only)
__device__ __nv_bfloat16 g_h_hi[2][(size_t)BATCH * DH];      // ping-pong split h
__device__ __nv_bfloat16 g_h_lo[2][(size_t)BATCH * DH];
__device__ __nv_bfloat16 g_wt_hi[(size_t)DH * DH];           // W1h^T split: wt[n][k]
__device__ __nv_bfloat16 g_wt_lo[(size_t)DH * DH];
__device__ __nv_bfloat16 g_xs_hi[(size_t)T_STEPS * BATCH * DIN];  // xs split
__device__ __nv_bfloat16 g_xs_lo[(size_t)T_STEPS * BATCH * DIN];
__device__ __nv_bfloat16 g_w1xt_hi[(size_t)DH * DIN];        // W1x^T split
__device__ __nv_bfloat16 g_w1xt_lo[(size_t)DH * DIN];
// per-(step, m-group) barrier slots, each padded to 128B (own L2 line)
__device__ int g_bar[T_STEPS * 4 * 32];

// ---------------- helpers ----------------
__device__ __forceinline__ uint32_t smem_u32(const void* p) {
    uint32_t a;
    asm("{ .reg .u64 t; cvta.to.shared.u64 t, %1; cvt.u32.u64 %0, t; }" : "=r"(a) : "l"(p));
    return a;
}
__device__ __forceinline__ void cp_async16(uint32_t dst, const void* src) {
    asm volatile("cp.async.cg.shared.global [%0], [%1], 16;" :: "r"(dst), "l"(src) : "memory");
}
__device__ __forceinline__ void cp_commit() {
    asm volatile("cp.async.commit_group;" ::: "memory");
}
__device__ __forceinline__ void cp_wait1() {
    asm volatile("cp.async.wait_group 1;" ::: "memory");
}
__device__ __forceinline__ void cp_wait0() {
    asm volatile("cp.async.wait_group 0;" ::: "memory");
}
__device__ __forceinline__ void ldmatrix_x4(uint32_t* r, uint32_t addr) {
    asm volatile("ldmatrix.sync.aligned.m8n8.x4.shared.b16 {%0,%1,%2,%3}, [%4];"
                 : "=r"(r[0]), "=r"(r[1]), "=r"(r[2]), "=r"(r[3]) : "r"(addr));
}
__device__ __forceinline__ void mma_bf16(float* c, const uint32_t* a,
                                         uint32_t b0, uint32_t b1) {
    asm volatile(
        "mma.sync.aligned.m16n8k16.row.col.f32.bf16.bf16.f32 "
        "{%0,%1,%2,%3},{%4,%5,%6,%7},{%8,%9},{%0,%1,%2,%3};"
        : "+f"(c[0]), "+f"(c[1]), "+f"(c[2]), "+f"(c[3])
        : "r"(a[0]), "r"(a[1]), "r"(a[2]), "r"(a[3]), "r"(b0), "r"(b1));
}
__device__ __forceinline__ float tanh_fast(float x) {
    float ax = fabsf(x);
    float e;
    asm("ex2.approx.f32 %0, %1;" : "=f"(e) : "f"(ax * -2.885390081777927f)); // e^{-2|x|}
    float r = __fdividef(1.0f - e, 1.0f + e);
    return __uint_as_float(__float_as_uint(r) | (__float_as_uint(x) & 0x80000000u));
}
__device__ __forceinline__ uint32_t prmt_hi(uint32_t x, uint32_t y) {
    uint32_t d;
    asm("prmt.b32 %0, %1, %2, 0x7632;" : "=r"(d) : "r"(x), "r"(y));
    return d;
}
__device__ __forceinline__ uint32_t cvt_bf16x2(float hi, float lo) {
    uint32_t d;
    asm("cvt.rn.bf16x2.f32 %0, %1, %2;" : "=r"(d) : "f"(hi), "f"(lo));
    return d;
}

// ---------------- utility kernels ----------------
__global__ void zero_u4(uint4* __restrict__ p, int n4) {
    int i = blockIdx.x * blockDim.x + threadIdx.x;
    if (i < n4) p[i] = make_uint4(0, 0, 0, 0);
}

__global__ void fsplit_kernel(const float* __restrict__ in,
                              __nv_bfloat16* __restrict__ hi,
                              __nv_bfloat16* __restrict__ lo, int n4) {
    int i = blockIdx.x * blockDim.x + threadIdx.x;
    if (i >= n4) return;
    float4 v = reinterpret_cast<const float4*>(in)[i];
    uint32_t u0 = __float_as_uint(v.x), u1 = __float_as_uint(v.y);
    uint32_t u2 = __float_as_uint(v.z), u3 = __float_as_uint(v.w);
    reinterpret_cast<uint2*>(hi)[i] = make_uint2(prmt_hi(u0, u1), prmt_hi(u2, u3));
    float l0 = v.x - __uint_as_float(u0 & 0xFFFF0000u);
    float l1 = v.y - __uint_as_float(u1 & 0xFFFF0000u);
    float l2 = v.z - __uint_as_float(u2 & 0xFFFF0000u);
    float l3 = v.w - __uint_as_float(u3 & 0xFFFF0000u);
    reinterpret_cast<uint2*>(lo)[i] = make_uint2(cvt_bf16x2(l1, l0), cvt_bf16x2(l3, l2));
}

// transpose + bf16 split: W[k][n] (KxN) -> out[n][k]
__global__ void wsplit_kernel(const float* __restrict__ W,
                              __nv_bfloat16* __restrict__ hi,
                              __nv_bfloat16* __restrict__ lo, int K, int N) {
    __shared__ float t[32][33];
    const int tx = threadIdx.x, ty = threadIdx.y;
    const int kb = blockIdx.y * 32, nb = blockIdx.x * 32;
#pragma unroll
    for (int i = 0; i < 32; i += 8)
        t[ty + i][tx] = W[(size_t)(kb + ty + i) * N + nb + tx];
    __syncthreads();
#pragma unroll
    for (int i = 0; i < 32; i += 8) {
        const int n = nb + ty + i, k = kb + tx;
        float v = t[tx][ty + i];
        __nv_bfloat16 h = __float2bfloat16(v);
        hi[(size_t)n * K + k] = h;
        lo[(size_t)n * K + k] = __float2bfloat16(v - __bfloat162float(h));
    }
}

// =====================================================================
// Persistent recurrence kernel, W resident in smem (R11, unchanged).
// grid 128 CTAs x 256 threads; CTA c: n0=(c&31)*32, m0=(c>>5)*64.
// 8 warps split-K (warp w owns k16 slice w of each 128-k tile).
// Step 0 skips the GEMM entirely (h(-1)=0 => out = tanh(Z[0])).
// =====================================================================
#define W_HI_OFF  0
#define W_LO_OFF  65536
#define ST_OFF    131072
#define ST_SZ     32768
#define SMEM_TOT  229376
#define RP 36
#define WBP 2308

__global__ void __launch_bounds__(256, 1)
rnn_persist(const __nv_bfloat16* __restrict__ hhi0, const __nv_bfloat16* __restrict__ hlo0,
            const __nv_bfloat16* __restrict__ wt_hi, const __nv_bfloat16* __restrict__ wt_lo,
            const float* __restrict__ Z, float* __restrict__ o_f,
            int* __restrict__ bar) {
    extern __shared__ __align__(128) char sm[];
    const uint32_t sb = smem_u32(sm);

    const int tid = threadIdx.x;
    const int w = tid >> 5;
    const int lane = tid & 31;
    const int cta = blockIdx.x;
    const int n0 = (cta & 31) * 32;
    const int m0 = (cta >> 5) * 64;
    const int mg = cta >> 5;
    const size_t HS = (size_t)BATCH * DH;

    // ---- load W slice into smem once ----
    {
#pragma unroll
        for (int i = 0; i < 16; i++) {
            const int c = tid + i * 256;
            const int row = c >> 7, u = c & 127;
            cp_async16(sb + W_HI_OFF + row * 2048 + ((u * 16) ^ ((row & 7) << 4)),
                       wt_hi + (size_t)(n0 + row) * DH + u * 8);
        }
#pragma unroll
        for (int i = 0; i < 16; i++) {
            const int c = tid + i * 256;
            const int row = c >> 7, u = c & 127;
            cp_async16(sb + W_LO_OFF + row * 2048 + ((u * 16) ^ ((row & 7) << 4)),
                       wt_lo + (size_t)(n0 + row) * DH + u * 8);
        }
        cp_commit();
    }

    // consumer addressing (constant across steps)
    const int l7 = lane & 7;
    const uint32_t xmk = (uint32_t)(l7 << 4);
    const int rowA = ((lane >> 3) & 1) * 8 + l7;
    const uint32_t kselA = ((lane >> 4) & 1) * 16;
    const int rowBb = ((lane >> 4) & 1) * 8 + l7;
    const uint32_t kselB = ((lane >> 3) & 1) * 16;
    const uint32_t wkb = (uint32_t)(w * 32);

    // epilogue addressing (constant)
    const int erow = tid >> 2;
    const int ec0 = (tid & 3) * 8;
    const size_t eoff = (size_t)(m0 + erow) * DH + n0 + ec0;

    for (int t = 0; t < T_STEPS; t++) {
        const int cur = t & 1;
        const __nv_bfloat16* h_hi = hhi0 + cur * HS;
        const __nv_bfloat16* h_lo = hlo0 + cur * HS;
        __nv_bfloat16* o_hi = const_cast<__nv_bfloat16*>(hhi0) + (cur ^ 1) * HS;
        __nv_bfloat16* o_lo = const_cast<__nv_bfloat16*>(hlo0) + (cur ^ 1) * HS;
        const float* Zt = Z + (size_t)t * HS;

        auto issue = [&](int kt, int buf) {
            const int k0 = kt << 7;
            const uint32_t st = sb + ST_OFF + buf * ST_SZ;
#pragma unroll
            for (int i = 0; i < 4; i++) {           // A_hi: 64 rows x 256B
                const int c = tid + (i << 8);
                const int row = c >> 4, u = c & 15;
                cp_async16(st + row * 256 + ((u * 16) ^ ((row & 7) << 4)),
                           h_hi + (size_t)(m0 + row) * DH + k0 + u * 8);
            }
#pragma unroll
            for (int i = 0; i < 4; i++) {           // A_lo
                const int c = tid + (i << 8);
                const int row = c >> 4, u = c & 15;
                cp_async16(st + 16384 + row * 256 + ((u * 16) ^ ((row & 7) << 4)),
                           h_lo + (size_t)(m0 + row) * DH + k0 + u * 8);
            }
        };

        float acc[4][4][4];
#pragma unroll
        for (int mt = 0; mt < 4; mt++)
#pragma unroll
            for (int n8 = 0; n8 < 4; n8++)
#pragma unroll
                for (int q = 0; q < 4; q++) acc[mt][n8][q] = 0.0f;

        auto compute = [&](int kt, int buf) {
            const uint32_t aHi = sb + ST_OFF + buf * ST_SZ;
            const uint32_t aLo = aHi + 16384;
            const uint32_t tkb = (uint32_t)(kt << 8);
            uint32_t ah[4][4], al[4][4], bh[2][4], bl[2][4];
#pragma unroll
            for (int mt = 0; mt < 4; mt++) {
                ldmatrix_x4(ah[mt], aHi + (mt * 16 + rowA) * 256 + ((wkb + kselA) ^ xmk));
                ldmatrix_x4(al[mt], aLo + (mt * 16 + rowA) * 256 + ((wkb + kselA) ^ xmk));
            }
#pragma unroll
            for (int nt = 0; nt < 2; nt++) {
                ldmatrix_x4(bh[nt], sb + W_HI_OFF + (nt * 16 + rowBb) * 2048 +
                                        ((tkb + wkb + kselB) ^ xmk));
                ldmatrix_x4(bl[nt], sb + W_LO_OFF + (nt * 16 + rowBb) * 2048 +
                                        ((tkb + wkb + kselB) ^ xmk));
            }
#pragma unroll
            for (int mt = 0; mt < 4; mt++)
#pragma unroll
                for (int nt = 0; nt < 2; nt++) {
                    mma_bf16(acc[mt][nt * 2],     ah[mt], bh[nt][0], bh[nt][1]);
                    mma_bf16(acc[mt][nt * 2 + 1], ah[mt], bh[nt][2], bh[nt][3]);
                    mma_bf16(acc[mt][nt * 2],     al[mt], bh[nt][0], bh[nt][1]);
                    mma_bf16(acc[mt][nt * 2 + 1], al[mt], bh[nt][2], bh[nt][3]);
                    mma_bf16(acc[mt][nt * 2],     ah[mt], bl[nt][0], bl[nt][1]);
                    mma_bf16(acc[mt][nt * 2 + 1], ah[mt], bl[nt][2], bl[nt][3]);
                }
        };

        // Z register prefetch (consumed in epilogue)
        const float4 zpre0 = *reinterpret_cast<const float4*>(Zt + eoff);
        const float4 zpre1 = *reinterpret_cast<const float4*>(Zt + eoff + 4);

        float* sred = reinterpret_cast<float*>(sm + ST_OFF);

        if (t > 0) {
            issue(0, 0); cp_commit();
            issue(1, 1); cp_commit();

            for (int kt = 0; kt < 8; kt++) {
                cp_wait1();
                __syncthreads();
                if (kt + 2 < 8) issue(kt + 2, (kt + 2) % 3);
                cp_commit();
                compute(kt, kt % 3);
            }

            // ---- cross-warp split-K reduction through smem ----
            cp_wait0();
            __syncthreads();
            float* ms = sred + w * WBP;
            const int g = lane >> 2, t4 = lane & 3;
#pragma unroll
            for (int mt = 0; mt < 4; mt++)
#pragma unroll
                for (int n8 = 0; n8 < 4; n8++) {
                    const int r0 = mt * 16 + g, c = n8 * 8 + 2 * t4;
                    *reinterpret_cast<float2*>(&ms[r0 * RP + c]) =
                        make_float2(acc[mt][n8][0], acc[mt][n8][1]);
                    *reinterpret_cast<float2*>(&ms[(r0 + 8) * RP + c]) =
                        make_float2(acc[mt][n8][2], acc[mt][n8][3]);
                }
            __syncthreads();
        }

        // ---- fused epilogue: sum 8 partials + Z, tanh, store splits ----
#pragma unroll
        for (int q = 0; q < 2; q++) {
            const int col = ec0 + q * 4;
            float4 s = make_float4(0.0f, 0.0f, 0.0f, 0.0f);
            if (t > 0) {
                s = *reinterpret_cast<const float4*>(&sred[erow * RP + col]);
#pragma unroll
                for (int w2 = 1; w2 < 8; w2++) {
                    float4 p = *reinterpret_cast<const float4*>(
                        &sred[w2 * WBP + erow * RP + col]);
                    s.x += p.x; s.y += p.y; s.z += p.z; s.w += p.w;
                }
            }
            const size_t off = eoff + q * 4;
            const float4 z = q ? zpre1 : zpre0;
            float v0 = tanh_fast(s.x + z.x);
            float v1 = tanh_fast(s.y + z.y);
            float v2 = tanh_fast(s.z + z.z);
            float v3 = tanh_fast(s.w + z.w);
            if (t == T_STEPS - 1)
                *reinterpret_cast<float4*>(o_f + off) = make_float4(v0, v1, v2, v3);
            uint32_t u0 = __float_as_uint(v0), u1 = __float_as_uint(v1);
            uint32_t u2 = __float_as_uint(v2), u3 = __float_as_uint(v3);
            *reinterpret_cast<uint2*>(o_hi + off) = make_uint2(prmt_hi(u0, u1), prmt_hi(u2, u3));
            float l0 = v0 - __uint_as_float(u0 & 0xFFFF0000u);
            float l1 = v1 - __uint_as_float(u1 & 0xFFFF0000u);
            float l2 = v2 - __uint_as_float(u2 & 0xFFFF0000u);
            float l3 = v3 - __uint_as_float(u3 & 0xFFFF0000u);
            *reinterpret_cast<uint2*>(o_lo + off) = make_uint2(cvt_bf16x2(l1, l0), cvt_bf16x2(l3, l2));
        }

        // ---- per-m-group barrier (32 arrivals; skip after last step) ----
        if (t < T_STEPS - 1) {
            __syncthreads();
            if (tid == 0) {
                int* slot = bar + (t * 4 + mg) * 32;
                asm volatile("red.release.gpu.global.add.s32 [%0], 1;" :: "l"(slot) : "memory");
                int v;
                do {
                    __nanosleep(32);
                    asm volatile("ld.acquire.gpu.global.b32 %0, [%1];" : "=r"(v) : "l"(slot) : "memory");
                } while (v < 32);
            }
            __syncthreads();
        }
    }
}

// =====================================================================
// Precompute kernel v3: Z = xs @ W1x + b1, fp32 via per-tile 3-term.
// CTA 128(M) x 64(N), grid (16, 256), 8 warps = 4m x 2n, occ 2.
// K = 4 tiles of 64; each tile loads A_hi+A_lo+B_hi+B_lo ONCE and does
// ah*bh + al*bh + ah*bl (xs_hi no longer re-read; -33% L2 traffic).
// 2-stage pipeline, 48KB/stage (A 32KB + B 16KB).
// =====================================================================
#define PST_SZ 49152

__global__ void __launch_bounds__(256, 2)
pre_hmma(const __nv_bfloat16* __restrict__ xs_hi, const __nv_bfloat16* __restrict__ xs_lo,
         const __nv_bfloat16* __restrict__ wx_hi, const __nv_bfloat16* __restrict__ wx_lo,
         const float* __restrict__ b1, float* __restrict__ Z) {
    extern __shared__ __align__(128) char pool[];   // 2 x 48KB stages

    const int tid = threadIdx.x;
    const int w = tid >> 5;
    const int lane = tid & 31;
    const int mw = w & 3, nw = w >> 2;
    const int n0 = blockIdx.x * 64;
    const int m0 = blockIdx.y * 128;
    const uint32_t base = smem_u32(pool);

    auto issue = [&](int kt, int buf) {
        const int k0 = kt << 6;
        const uint32_t st = base + buf * PST_SZ;
#pragma unroll
        for (int i = 0; i < 4; i++) {               // A_hi: 128 rows x 128B
            const int c = tid + (i << 8);
            const int row = c >> 3, u = c & 7;
            cp_async16(st + row * 128 + ((u * 16) ^ ((row & 7) << 4)),
                       xs_hi + (size_t)(m0 + row) * DIN + k0 + u * 8);
        }
#pragma unroll
        for (int i = 0; i < 4; i++) {               // A_lo
            const int c = tid + (i << 8);
            const int row = c >> 3, u = c & 7;
            cp_async16(st + 16384 + row * 128 + ((u * 16) ^ ((row & 7) << 4)),
                       xs_lo + (size_t)(m0 + row) * DIN + k0 + u * 8);
        }
#pragma unroll
        for (int i = 0; i < 2; i++) {               // B_hi: 64 rows x 128B
            const int c = tid + (i << 8);
            const int row = c >> 3, u = c & 7;
            cp_async16(st + 32768 + row * 128 + ((u * 16) ^ ((row & 7) << 4)),
                       wx_hi + (size_t)(n0 + row) * DIN + k0 + u * 8);
        }
#pragma unroll
        for (int i = 0; i < 2; i++) {               // B_lo
            const int c = tid + (i << 8);
            const int row = c >> 3, u = c & 7;
            cp_async16(st + 40960 + row * 128 + ((u * 16) ^ ((row & 7) << 4)),
                       wx_lo + (size_t)(n0 + row) * DIN + k0 + u * 8);
        }
    };

    const int l7 = lane & 7;
    const uint32_t xmk = (uint32_t)(l7 << 4);
    const int rowA = ((lane >> 3) & 1) * 8 + l7;
    const uint32_t kselA = ((lane >> 4) & 1) * 16;
    const int rowBb = ((lane >> 4) & 1) * 8 + l7;
    const uint32_t kselB = ((lane >> 3) & 1) * 16;

    float acc[2][4][4];
#pragma unroll
    for (int mt = 0; mt < 2; mt++)
#pragma unroll
        for (int n8 = 0; n8 < 4; n8++)
#pragma unroll
            for (int q = 0; q < 4; q++) acc[mt][n8][q] = 0.0f;

    auto compute = [&](int buf) {
        const uint32_t st = base + buf * PST_SZ;
        const uint32_t aHi = st, aLo = st + 16384;
        const uint32_t bHi = st + 32768, bLo = st + 40960;
#pragma unroll
        for (int k16 = 0; k16 < 4; k16++) {
            const uint32_t kb = (uint32_t)(k16 * 32);
            uint32_t ah[2][4], al[2][4];
#pragma unroll
            for (int mt = 0; mt < 2; mt++) {
                ldmatrix_x4(ah[mt], aHi + (mw * 32 + mt * 16 + rowA) * 128 + ((kb + kselA) ^ xmk));
                ldmatrix_x4(al[mt], aLo + (mw * 32 + mt * 16 + rowA) * 128 + ((kb + kselA) ^ xmk));
            }
#pragma unroll
            for (int nt = 0; nt < 2; nt++) {
                uint32_t bh[4], bl[4];
                ldmatrix_x4(bh, bHi + (nw * 32 + nt * 16 + rowBb) * 128 + ((kb + kselB) ^ xmk));
                ldmatrix_x4(bl, bLo + (nw * 32 + nt * 16 + rowBb) * 128 + ((kb + kselB) ^ xmk));
#pragma unroll
                for (int mt = 0; mt < 2; mt++) {
                    mma_bf16(acc[mt][nt * 2],     ah[mt], bh[0], bh[1]);
                    mma_bf16(acc[mt][nt * 2 + 1], ah[mt], bh[2], bh[3]);
                    mma_bf16(acc[mt][nt * 2],     al[mt], bh[0], bh[1]);
                    mma_bf16(acc[mt][nt * 2 + 1], al[mt], bh[2], bh[3]);
                    mma_bf16(acc[mt][nt * 2],     ah[mt], bl[0], bl[1]);
                    mma_bf16(acc[mt][nt * 2 + 1], ah[mt], bl[2], bl[3]);
                }
            }
        }
    };

    issue(0, 0); cp_commit();
    issue(1, 1); cp_commit();
    for (int kt = 0; kt < 4; kt++) {
        if (kt == 3) cp_wait0(); else cp_wait1();
        __syncthreads();
        compute(kt & 1);
        if (kt + 2 < 4) {
            __syncthreads();
            issue(kt + 2, kt & 1);
            cp_commit();
        }
    }

    // epilogue: + b1, write fp32 Z (fragment-wise)
    const int g = lane >> 2, t4 = lane & 3;
#pragma unroll
    for (int mt = 0; mt < 2; mt++)
#pragma unroll
        for (int n8 = 0; n8 < 4; n8++) {
            const float* c = acc[mt][n8];
            const int col = n0 + nw * 32 + n8 * 8 + 2 * t4;
            const int r0 = m0 + mw * 32 + mt * 16 + g;
            const size_t o0 = (size_t)r0 * DH + col;
            const size_t o1 = o0 + 8 * DH;
            float2 bi = *reinterpret_cast<const float2*>(b1 + col);
            *reinterpret_cast<float2*>(Z + o0) = make_float2(c[0] + bi.x, c[1] + bi.y);
            *reinterpret_cast<float2*>(Z + o1) = make_float2(c[2] + bi.x, c[3] + bi.y);
        }
}

// ---------------- packed f32x2 GEMM (readout only) ----------------
__device__ __forceinline__ void fma2(unsigned long long& acc,
                                     unsigned long long a, unsigned long long b) {
    asm("fma.rn.f32x2 %0, %1, %2, %0;" : "+l"(acc) : "l"(a), "l"(b));
}
__device__ __forceinline__ unsigned long long pack2(float x, float y) {
    unsigned long long r;
    asm("mov.b64 %0, {%1, %2};" : "=l"(r) : "f"(x), "f"(y));
    return r;
}
__device__ __forceinline__ float2 unpack2(unsigned long long v) {
    float2 f;
    asm("mov.b64 {%0, %1}, %2;" : "=f"(f.x), "=f"(f.y) : "l"(v));
    return f;
}

template <int BM, int BN, int BK, int TM>
__global__ void __launch_bounds__(256)
gemm_f32x2(const float* __restrict__ A, const float* __restrict__ Bm,
           const float* __restrict__ aux, float* __restrict__ C,
           int M, int N, int K) {
    constexpr int TN = 4;
    constexpr int NT = (BM / TM) * (BN / TN);
    static_assert(NT == 256, "block must be 256 threads");
    __shared__ float As[BK][BM + 4];
    __shared__ float Bs[BK][BN];

    const int tid = threadIdx.x;
    const int n0 = blockIdx.x * BN;
    const int m0 = blockIdx.y * BM;
    constexpr int A_PER = (BM * BK / 4) / NT;
    constexpr int B_PER = (BK * BN / 4) / NT;
    float4 ar[A_PER], br[B_PER];

    auto loadA = [&](int kt) {
#pragma unroll
        for (int i = 0; i < A_PER; i++) {
            int idx = tid + i * NT, row = idx / (BK / 4), kc = idx % (BK / 4);
            ar[i] = *reinterpret_cast<const float4*>(&A[(size_t)(m0 + row) * K + kt * BK + kc * 4]);
        }
    };
    auto storeA = [&]() {
#pragma unroll
        for (int i = 0; i < A_PER; i++) {
            int idx = tid + i * NT, row = idx / (BK / 4), kc = idx % (BK / 4);
            As[kc * 4 + 0][row] = ar[i].x; As[kc * 4 + 1][row] = ar[i].y;
            As[kc * 4 + 2][row] = ar[i].z; As[kc * 4 + 3][row] = ar[i].w;
        }
    };
    auto loadB = [&](int kt) {
#pragma unroll
        for (int i = 0; i < B_PER; i++) {
            int idx = tid + i * NT, kr = idx / (BN / 4), nc = idx % (BN / 4);
            br[i] = *reinterpret_cast<const float4*>(&Bm[(size_t)(kt * BK + kr) * N + n0 + nc * 4]);
        }
    };
    auto storeB = [&]() {
#pragma unroll
        for (int i = 0; i < B_PER; i++) {
            int idx = tid + i * NT, kr = idx / (BN / 4), nc = idx % (BN / 4);
            *reinterpret_cast<float4*>(&Bs[kr][nc * 4]) = br[i];
        }
    };

    unsigned long long acc[TM][2];
#pragma unroll
    for (int i = 0; i < TM; i++) { acc[i][0] = pack2(0, 0); acc[i][1] = pack2(0, 0); }

    const int rg = tid / (BN / TN), cg = tid % (BN / TN);
    const int r0 = rg * TM, c0 = cg * TN;
    const int nk = K / BK;
    loadA(0); loadB(0); storeA(); storeB();
    __syncthreads();
    for (int kt = 0; kt < nk; kt++) {
        if (kt + 1 < nk) { loadA(kt + 1); loadB(kt + 1); }
#pragma unroll
        for (int k = 0; k < BK; k++) {
            float a[TM];
            if (TM == 2) {
                float2 avv = *reinterpret_cast<const float2*>(&As[k][r0]);
                a[0] = avv.x; a[1] = avv.y;
            } else {
                float4 avv = *reinterpret_cast<const float4*>(&As[k][r0]);
                a[0] = avv.x; a[1] = avv.y; a[2] = avv.z; a[3] = avv.w;
            }
            float4 bvv = *reinterpret_cast<const float4*>(&Bs[k][c0]);
            unsigned long long b01 = pack2(bvv.x, bvv.y), b23 = pack2(bvv.z, bvv.w);
#pragma unroll
            for (int i = 0; i < TM; i++) {
                unsigned long long aa = pack2(a[i], a[i]);
                fma2(acc[i][0], aa, b01);
                fma2(acc[i][1], aa, b23);
            }
        }
        __syncthreads();
        if (kt + 1 < nk) { storeA(); storeB(); __syncthreads(); }
    }
#pragma unroll
    for (int i = 0; i < TM; i++) {
        float2 p0 = unpack2(acc[i][0]), p1 = unpack2(acc[i][1]);
        float4 v = make_float4(p0.x, p0.y, p1.x, p1.y);
        const int row = m0 + r0 + i, col = n0 + c0;
        const size_t off = (size_t)row * N + col;
        float s = aux[0];
        v.x += s; v.y += s; v.z += s; v.w += s;
        *reinterpret_cast<float4*>(&C[off]) = v;
    }
}

// ---------------- host launcher ----------------
extern "C" void kernel_launch(void* const* d_in, const int* in_sizes, int n_in,
                              void* d_out, int out_size) {
    const float* xs  = (const float*)d_in[0];
    const float* W1x = (const float*)d_in[1];
    const float* W1h = (const float*)d_in[2];
    const float* b1  = (const float*)d_in[3];
    const float* W2  = (const float*)d_in[4];
    const float* b2  = (const float*)d_in[5];
    float* out = (float*)d_out;

    float *zp, *hf;
    int* barp;
    __nv_bfloat16 *hhi, *hlo, *wthi, *wtlo, *xshi, *xslo, *wxhi, *wxlo;
    cudaGetSymbolAddress((void**)&zp, g_z);
    cudaGetSymbolAddress((void**)&hf, g_hf);
    cudaGetSymbolAddress((void**)&hhi, g_h_hi);
    cudaGetSymbolAddress((void**)&hlo, g_h_lo);
    cudaGetSymbolAddress((void**)&wthi, g_wt_hi);
    cudaGetSymbolAddress((void**)&wtlo, g_wt_lo);
    cudaGetSymbolAddress((void**)&xshi, g_xs_hi);
    cudaGetSymbolAddress((void**)&xslo, g_xs_lo);
    cudaGetSymbolAddress((void**)&wxhi, g_w1xt_hi);
    cudaGetSymbolAddress((void**)&wxlo, g_w1xt_lo);
    cudaGetSymbolAddress((void**)&barp, g_bar);

    cudaFuncSetAttribute(pre_hmma, cudaFuncAttributeMaxDynamicSharedMemorySize, 2 * PST_SZ);
    cudaFuncSetAttribute(rnn_persist, cudaFuncAttributeMaxDynamicSharedMemorySize, SMEM_TOT);

    const int XN = T_STEPS * BATCH * DIN;

    // splits
    fsplit_kernel<<<XN / 4 / 256, 256>>>(xs, xshi, xslo, XN / 4);
    wsplit_kernel<<<dim3(DH / 32, DIN / 32), dim3(32, 8)>>>(W1x, wxhi, wxlo, DIN, DH);
    wsplit_kernel<<<dim3(DH / 32, DH / 32), dim3(32, 8)>>>(W1h, wthi, wtlo, DH, DH);

    // zero barrier slots (h buffers not needed: step 0 skips the GEMM)
    zero_u4<<<16, 256>>>((uint4*)barp, T_STEPS * 4 * 32 / 4);

    // Z = xs@W1x + b1 (HMMA, per-tile 3-term)
    pre_hmma<<<dim3(16, 256), 256, 2 * PST_SZ>>>(xshi, xslo, wxhi, wxlo, b1, zp);

    // full recurrence in one persistent launch (W resident, per-mg barrier)
    rnn_persist<<<128, 256, SMEM_TOT>>>(hhi, hlo, wthi, wtlo, zp, hf, barp);

    // out = h_final @ W2 + b2
    gemm_f32x2<32, 64, 32, 2>
        <<<dim3(DOUT / 64, BATCH / 32), 256>>>(hf, W2, b2, out, BATCH, DOUT, DH);
}

// round 14
// speedup vs baseline: 1.2301x; 1.0094x over previous
#include <cuda_runtime.h>
#include <cuda_bf16.h>
#include <math.h>
#include <stdint.h>

#define T_STEPS 128
#define BATCH   256
#define DIN     256
#define DH      1024
#define DOUT    256

// ---------------- device scratch ----------------
__device__ float g_z[(size_t)T_STEPS * BATCH * DH];          // 134 MB: xs@W1x + b1
__device__ float g_hf[(size_t)BATCH * DH];                   // fp32 h (final step only)
__device__ __nv_bfloat16 g_h_hi[2][(size_t)BATCH * DH];      // ping-pong split h
__device__ __nv_bfloat16 g_h_lo[2][(size_t)BATCH * DH];
__device__ __nv_bfloat16 g_wt_hi[(size_t)DH * DH];           // W1h^T split: wt[n][k]
__device__ __nv_bfloat16 g_wt_lo[(size_t)DH * DH];
__device__ __nv_bfloat16 g_xs_hi[(size_t)T_STEPS * BATCH * DIN];  // xs split
__device__ __nv_bfloat16 g_xs_lo[(size_t)T_STEPS * BATCH * DIN];
__device__ __nv_bfloat16 g_w1xt_hi[(size_t)DH * DIN];        // W1x^T split
__device__ __nv_bfloat16 g_w1xt_lo[(size_t)DH * DIN];
// per-(step, m-group) barrier slots, each padded to 128B (own L2 line)
__device__ int g_bar[T_STEPS * 4 * 32];

// ---------------- helpers ----------------
__device__ __forceinline__ uint32_t smem_u32(const void* p) {
    uint32_t a;
    asm("{ .reg .u64 t; cvta.to.shared.u64 t, %1; cvt.u32.u64 %0, t; }" : "=r"(a) : "l"(p));
    return a;
}
__device__ __forceinline__ void cp_async16(uint32_t dst, const void* src) {
    asm volatile("cp.async.cg.shared.global [%0], [%1], 16;" :: "r"(dst), "l"(src) : "memory");
}
__device__ __forceinline__ void cp_commit() {
    asm volatile("cp.async.commit_group;" ::: "memory");
}
__device__ __forceinline__ void cp_wait1() {
    asm volatile("cp.async.wait_group 1;" ::: "memory");
}
__device__ __forceinline__ void cp_wait0() {
    asm volatile("cp.async.wait_group 0;" ::: "memory");
}
__device__ __forceinline__ void ldmatrix_x4(uint32_t* r, uint32_t addr) {
    asm volatile("ldmatrix.sync.aligned.m8n8.x4.shared.b16 {%0,%1,%2,%3}, [%4];"
                 : "=r"(r[0]), "=r"(r[1]), "=r"(r[2]), "=r"(r[3]) : "r"(addr));
}
__device__ __forceinline__ void mma_bf16(float* c, const uint32_t* a,
                                         uint32_t b0, uint32_t b1) {
    asm volatile(
        "mma.sync.aligned.m16n8k16.row.col.f32.bf16.bf16.f32 "
        "{%0,%1,%2,%3},{%4,%5,%6,%7},{%8,%9},{%0,%1,%2,%3};"
        : "+f"(c[0]), "+f"(c[1]), "+f"(c[2]), "+f"(c[3])
        : "r"(a[0]), "r"(a[1]), "r"(a[2]), "r"(a[3]), "r"(b0), "r"(b1));
}
__device__ __forceinline__ float tanh_fast(float x) {
    float ax = fabsf(x);
    float e;
    asm("ex2.approx.f32 %0, %1;" : "=f"(e) : "f"(ax * -2.885390081777927f)); // e^{-2|x|}
    float r = __fdividef(1.0f - e, 1.0f + e);
    return __uint_as_float(__float_as_uint(r) | (__float_as_uint(x) & 0x80000000u));
}
__device__ __forceinline__ uint32_t prmt_hi(uint32_t x, uint32_t y) {
    uint32_t d;
    asm("prmt.b32 %0, %1, %2, 0x7632;" : "=r"(d) : "r"(x), "r"(y));
    return d;
}
__device__ __forceinline__ uint32_t cvt_bf16x2(float hi, float lo) {
    uint32_t d;
    asm("cvt.rn.bf16x2.f32 %0, %1, %2;" : "=r"(d) : "f"(hi), "f"(lo));
    return d;
}

// ---------------- utility kernels ----------------
__global__ void zero_u4(uint4* __restrict__ p, int n4) {
    int i = blockIdx.x * blockDim.x + threadIdx.x;
    if (i < n4) p[i] = make_uint4(0, 0, 0, 0);
}

__global__ void fsplit_kernel(const float* __restrict__ in,
                              __nv_bfloat16* __restrict__ hi,
                              __nv_bfloat16* __restrict__ lo, int n4) {
    int i = blockIdx.x * blockDim.x + threadIdx.x;
    if (i >= n4) return;
    float4 v = reinterpret_cast<const float4*>(in)[i];
    uint32_t u0 = __float_as_uint(v.x), u1 = __float_as_uint(v.y);
    uint32_t u2 = __float_as_uint(v.z), u3 = __float_as_uint(v.w);
    reinterpret_cast<uint2*>(hi)[i] = make_uint2(prmt_hi(u0, u1), prmt_hi(u2, u3));
    float l0 = v.x - __uint_as_float(u0 & 0xFFFF0000u);
    float l1 = v.y - __uint_as_float(u1 & 0xFFFF0000u);
    float l2 = v.z - __uint_as_float(u2 & 0xFFFF0000u);
    float l3 = v.w - __uint_as_float(u3 & 0xFFFF0000u);
    reinterpret_cast<uint2*>(lo)[i] = make_uint2(cvt_bf16x2(l1, l0), cvt_bf16x2(l3, l2));
}

// transpose + bf16 split: W[k][n] (KxN) -> out[n][k]
__global__ void wsplit_kernel(const float* __restrict__ W,
                              __nv_bfloat16* __restrict__ hi,
                              __nv_bfloat16* __restrict__ lo, int K, int N) {
    __shared__ float t[32][33];
    const int tx = threadIdx.x, ty = threadIdx.y;
    const int kb = blockIdx.y * 32, nb = blockIdx.x * 32;
#pragma unroll
    for (int i = 0; i < 32; i += 8)
        t[ty + i][tx] = W[(size_t)(kb + ty + i) * N + nb + tx];
    __syncthreads();
#pragma unroll
    for (int i = 0; i < 32; i += 8) {
        const int n = nb + ty + i, k = kb + tx;
        float v = t[tx][ty + i];
        __nv_bfloat16 h = __float2bfloat16(v);
        hi[(size_t)n * K + k] = h;
        lo[(size_t)n * K + k] = __float2bfloat16(v - __bfloat162float(h));
    }
}

// =====================================================================
// Persistent recurrence kernel, W resident in smem.
// grid 128 CTAs x 256 threads; CTA c: n0=(c&31)*32, m0=(c>>5)*64.
// 8 warps split-K (warp w owns k16 slice w of each 128-k tile).
// Step 0 skips the GEMM entirely (h(-1)=0 => out = tanh(Z[0])).
// Z for step t+1 prefetched BEFORE the step-t barrier (hidden latency).
// =====================================================================
#define W_HI_OFF  0
#define W_LO_OFF  65536
#define ST_OFF    131072
#define ST_SZ     32768
#define SMEM_TOT  229376
#define RP 36
#define WBP 2308

__global__ void __launch_bounds__(256, 1)
rnn_persist(const __nv_bfloat16* __restrict__ hhi0, const __nv_bfloat16* __restrict__ hlo0,
            const __nv_bfloat16* __restrict__ wt_hi, const __nv_bfloat16* __restrict__ wt_lo,
            const float* __restrict__ Z, float* __restrict__ o_f,
            int* __restrict__ bar) {
    extern __shared__ __align__(128) char sm[];
    const uint32_t sb = smem_u32(sm);

    const int tid = threadIdx.x;
    const int w = tid >> 5;
    const int lane = tid & 31;
    const int cta = blockIdx.x;
    const int n0 = (cta & 31) * 32;
    const int m0 = (cta >> 5) * 64;
    const int mg = cta >> 5;
    const size_t HS = (size_t)BATCH * DH;

    // ---- load W slice into smem once ----
    {
#pragma unroll
        for (int i = 0; i < 16; i++) {
            const int c = tid + i * 256;
            const int row = c >> 7, u = c & 127;
            cp_async16(sb + W_HI_OFF + row * 2048 + ((u * 16) ^ ((row & 7) << 4)),
                       wt_hi + (size_t)(n0 + row) * DH + u * 8);
        }
#pragma unroll
        for (int i = 0; i < 16; i++) {
            const int c = tid + i * 256;
            const int row = c >> 7, u = c & 127;
            cp_async16(sb + W_LO_OFF + row * 2048 + ((u * 16) ^ ((row & 7) << 4)),
                       wt_lo + (size_t)(n0 + row) * DH + u * 8);
        }
        cp_commit();
    }

    // consumer addressing (constant across steps)
    const int l7 = lane & 7;
    const uint32_t xmk = (uint32_t)(l7 << 4);
    const int rowA = ((lane >> 3) & 1) * 8 + l7;
    const uint32_t kselA = ((lane >> 4) & 1) * 16;
    const int rowBb = ((lane >> 4) & 1) * 8 + l7;
    const uint32_t kselB = ((lane >> 3) & 1) * 16;
    const uint32_t wkb = (uint32_t)(w * 32);

    // epilogue addressing (constant)
    const int erow = tid >> 2;
    const int ec0 = (tid & 3) * 8;
    const size_t eoff = (size_t)(m0 + erow) * DH + n0 + ec0;

    // Z prefetch for step 0
    float4 zpre0 = *reinterpret_cast<const float4*>(Z + eoff);
    float4 zpre1 = *reinterpret_cast<const float4*>(Z + eoff + 4);

    for (int t = 0; t < T_STEPS; t++) {
        const int cur = t & 1;
        const __nv_bfloat16* h_hi = hhi0 + cur * HS;
        const __nv_bfloat16* h_lo = hlo0 + cur * HS;
        __nv_bfloat16* o_hi = const_cast<__nv_bfloat16*>(hhi0) + (cur ^ 1) * HS;
        __nv_bfloat16* o_lo = const_cast<__nv_bfloat16*>(hlo0) + (cur ^ 1) * HS;

        auto issue = [&](int kt, int buf) {
            const int k0 = kt << 7;
            const uint32_t st = sb + ST_OFF + buf * ST_SZ;
#pragma unroll
            for (int i = 0; i < 4; i++) {           // A_hi: 64 rows x 256B
                const int c = tid + (i << 8);
                const int row = c >> 4, u = c & 15;
                cp_async16(st + row * 256 + ((u * 16) ^ ((row & 7) << 4)),
                           h_hi + (size_t)(m0 + row) * DH + k0 + u * 8);
            }
#pragma unroll
            for (int i = 0; i < 4; i++) {           // A_lo
                const int c = tid + (i << 8);
                const int row = c >> 4, u = c & 15;
                cp_async16(st + 16384 + row * 256 + ((u * 16) ^ ((row & 7) << 4)),
                           h_lo + (size_t)(m0 + row) * DH + k0 + u * 8);
            }
        };

        float acc[4][4][4];
#pragma unroll
        for (int mt = 0; mt < 4; mt++)
#pragma unroll
            for (int n8 = 0; n8 < 4; n8++)
#pragma unroll
                for (int q = 0; q < 4; q++) acc[mt][n8][q] = 0.0f;

        auto compute = [&](int kt, int buf) {
            const uint32_t aHi = sb + ST_OFF + buf * ST_SZ;
            const uint32_t aLo = aHi + 16384;
            const uint32_t tkb = (uint32_t)(kt << 8);
            uint32_t ah[4][4], al[4][4], bh[2][4], bl[2][4];
#pragma unroll
            for (int mt = 0; mt < 4; mt++) {
                ldmatrix_x4(ah[mt], aHi + (mt * 16 + rowA) * 256 + ((wkb + kselA) ^ xmk));
                ldmatrix_x4(al[mt], aLo + (mt * 16 + rowA) * 256 + ((wkb + kselA) ^ xmk));
            }
#pragma unroll
            for (int nt = 0; nt < 2; nt++) {
                ldmatrix_x4(bh[nt], sb + W_HI_OFF + (nt * 16 + rowBb) * 2048 +
                                        ((tkb + wkb + kselB) ^ xmk));
                ldmatrix_x4(bl[nt], sb + W_LO_OFF + (nt * 16 + rowBb) * 2048 +
                                        ((tkb + wkb + kselB) ^ xmk));
            }
#pragma unroll
            for (int mt = 0; mt < 4; mt++)
#pragma unroll
                for (int nt = 0; nt < 2; nt++) {
                    mma_bf16(acc[mt][nt * 2],     ah[mt], bh[nt][0], bh[nt][1]);
                    mma_bf16(acc[mt][nt * 2 + 1], ah[mt], bh[nt][2], bh[nt][3]);
                    mma_bf16(acc[mt][nt * 2],     al[mt], bh[nt][0], bh[nt][1]);
                    mma_bf16(acc[mt][nt * 2 + 1], al[mt], bh[nt][2], bh[nt][3]);
                    mma_bf16(acc[mt][nt * 2],     ah[mt], bl[nt][0], bl[nt][1]);
                    mma_bf16(acc[mt][nt * 2 + 1], ah[mt], bl[nt][2], bl[nt][3]);
                }
        };

        float* sred = reinterpret_cast<float*>(sm + ST_OFF);

        if (t > 0) {
            issue(0, 0); cp_commit();
            issue(1, 1); cp_commit();

            for (int kt = 0; kt < 8; kt++) {
                cp_wait1();
                __syncthreads();
                if (kt + 2 < 8) issue(kt + 2, (kt + 2) % 3);
                cp_commit();
                compute(kt, kt % 3);
            }

            // ---- cross-warp split-K reduction through smem ----
            cp_wait0();
            __syncthreads();
            float* ms = sred + w * WBP;
            const int g = lane >> 2, t4 = lane & 3;
#pragma unroll
            for (int mt = 0; mt < 4; mt++)
#pragma unroll
                for (int n8 = 0; n8 < 4; n8++) {
                    const int r0 = mt * 16 + g, c = n8 * 8 + 2 * t4;
                    *reinterpret_cast<float2*>(&ms[r0 * RP + c]) =
                        make_float2(acc[mt][n8][0], acc[mt][n8][1]);
                    *reinterpret_cast<float2*>(&ms[(r0 + 8) * RP + c]) =
                        make_float2(acc[mt][n8][2], acc[mt][n8][3]);
                }
            __syncthreads();
        }

        // ---- fused epilogue: sum 8 partials + Z, tanh, store splits ----
#pragma unroll
        for (int q = 0; q < 2; q++) {
            const int col = ec0 + q * 4;
            float4 s = make_float4(0.0f, 0.0f, 0.0f, 0.0f);
            if (t > 0) {
                s = *reinterpret_cast<const float4*>(&sred[erow * RP + col]);
#pragma unroll
                for (int w2 = 1; w2 < 8; w2++) {
                    float4 p = *reinterpret_cast<const float4*>(
                        &sred[w2 * WBP + erow * RP + col]);
                    s.x += p.x; s.y += p.y; s.z += p.z; s.w += p.w;
                }
            }
            const size_t off = eoff + q * 4;
            const float4 z = q ? zpre1 : zpre0;
            float v0 = tanh_fast(s.x + z.x);
            float v1 = tanh_fast(s.y + z.y);
            float v2 = tanh_fast(s.z + z.z);
            float v3 = tanh_fast(s.w + z.w);
            if (t == T_STEPS - 1)
                *reinterpret_cast<float4*>(o_f + off) = make_float4(v0, v1, v2, v3);
            uint32_t u0 = __float_as_uint(v0), u1 = __float_as_uint(v1);
            uint32_t u2 = __float_as_uint(v2), u3 = __float_as_uint(v3);
            *reinterpret_cast<uint2*>(o_hi + off) = make_uint2(prmt_hi(u0, u1), prmt_hi(u2, u3));
            float l0 = v0 - __uint_as_float(u0 & 0xFFFF0000u);
            float l1 = v1 - __uint_as_float(u1 & 0xFFFF0000u);
            float l2 = v2 - __uint_as_float(u2 & 0xFFFF0000u);
            float l3 = v3 - __uint_as_float(u3 & 0xFFFF0000u);
            *reinterpret_cast<uint2*>(o_lo + off) = make_uint2(cvt_bf16x2(l1, l0), cvt_bf16x2(l3, l2));
        }

        // ---- prefetch next step's Z, then per-m-group barrier ----
        if (t < T_STEPS - 1) {
            const float* Zn = Z + (size_t)(t + 1) * HS;
            float4 znx0 = *reinterpret_cast<const float4*>(Zn + eoff);
            float4 znx1 = *reinterpret_cast<const float4*>(Zn + eoff + 4);
            __syncthreads();
            if (tid == 0) {
                int* slot = bar + (t * 4 + mg) * 32;
                asm volatile("red.release.gpu.global.add.s32 [%0], 1;" :: "l"(slot) : "memory");
                int v;
                do {
                    __nanosleep(16);
                    asm volatile("ld.acquire.gpu.global.b32 %0, [%1];" : "=r"(v) : "l"(slot) : "memory");
                } while (v < 32);
            }
            __syncthreads();
            zpre0 = znx0;
            zpre1 = znx1;
        }
    }
}

// =====================================================================
// Precompute kernel v3: Z = xs @ W1x + b1, fp32 via per-tile 3-term.
// CTA 128(M) x 64(N), grid (16, 256), 8 warps = 4m x 2n, occ 2.
// =====================================================================
#define PST_SZ 49152

__global__ void __launch_bounds__(256, 2)
pre_hmma(const __nv_bfloat16* __restrict__ xs_hi, const __nv_bfloat16* __restrict__ xs_lo,
         const __nv_bfloat16* __restrict__ wx_hi, const __nv_bfloat16* __restrict__ wx_lo,
         const float* __restrict__ b1, float* __restrict__ Z) {
    extern __shared__ __align__(128) char pool[];   // 2 x 48KB stages

    const int tid = threadIdx.x;
    const int w = tid >> 5;
    const int lane = tid & 31;
    const int mw = w & 3, nw = w >> 2;
    const int n0 = blockIdx.x * 64;
    const int m0 = blockIdx.y * 128;
    const uint32_t base = smem_u32(pool);

    auto issue = [&](int kt, int buf) {
        const int k0 = kt << 6;
        const uint32_t st = base + buf * PST_SZ;
#pragma unroll
        for (int i = 0; i < 4; i++) {               // A_hi: 128 rows x 128B
            const int c = tid + (i << 8);
            const int row = c >> 3, u = c & 7;
            cp_async16(st + row * 128 + ((u * 16) ^ ((row & 7) << 4)),
                       xs_hi + (size_t)(m0 + row) * DIN + k0 + u * 8);
        }
#pragma unroll
        for (int i = 0; i < 4; i++) {               // A_lo
            const int c = tid + (i << 8);
            const int row = c >> 3, u = c & 7;
            cp_async16(st + 16384 + row * 128 + ((u * 16) ^ ((row & 7) << 4)),
                       xs_lo + (size_t)(m0 + row) * DIN + k0 + u * 8);
        }
#pragma unroll
        for (int i = 0; i < 2; i++) {               // B_hi: 64 rows x 128B
            const int c = tid + (i << 8);
            const int row = c >> 3, u = c & 7;
            cp_async16(st + 32768 + row * 128 + ((u * 16) ^ ((row & 7) << 4)),
                       wx_hi + (size_t)(n0 + row) * DIN + k0 + u * 8);
        }
#pragma unroll
        for (int i = 0; i < 2; i++) {               // B_lo
            const int c = tid + (i << 8);
            const int row = c >> 3, u = c & 7;
            cp_async16(st + 40960 + row * 128 + ((u * 16) ^ ((row & 7) << 4)),
                       wx_lo + (size_t)(n0 + row) * DIN + k0 + u * 8);
        }
    };

    const int l7 = lane & 7;
    const uint32_t xmk = (uint32_t)(l7 << 4);
    const int rowA = ((lane >> 3) & 1) * 8 + l7;
    const uint32_t kselA = ((lane >> 4) & 1) * 16;
    const int rowBb = ((lane >> 4) & 1) * 8 + l7;
    const uint32_t kselB = ((lane >> 3) & 1) * 16;

    float acc[2][4][4];
#pragma unroll
    for (int mt = 0; mt < 2; mt++)
#pragma unroll
        for (int n8 = 0; n8 < 4; n8++)
#pragma unroll
            for (int q = 0; q < 4; q++) acc[mt][n8][q] = 0.0f;

    auto compute = [&](int buf) {
        const uint32_t st = base + buf * PST_SZ;
        const uint32_t aHi = st, aLo = st + 16384;
        const uint32_t bHi = st + 32768, bLo = st + 40960;
#pragma unroll
        for (int k16 = 0; k16 < 4; k16++) {
            const uint32_t kb = (uint32_t)(k16 * 32);
            uint32_t ah[2][4], al[2][4];
#pragma unroll
            for (int mt = 0; mt < 2; mt++) {
                ldmatrix_x4(ah[mt], aHi + (mw * 32 + mt * 16 + rowA) * 128 + ((kb + kselA) ^ xmk));
                ldmatrix_x4(al[mt], aLo + (mw * 32 + mt * 16 + rowA) * 128 + ((kb + kselA) ^ xmk));
            }
#pragma unroll
            for (int nt = 0; nt < 2; nt++) {
                uint32_t bh[4], bl[4];
                ldmatrix_x4(bh, bHi + (nw * 32 + nt * 16 + rowBb) * 128 + ((kb + kselB) ^ xmk));
                ldmatrix_x4(bl, bLo + (nw * 32 + nt * 16 + rowBb) * 128 + ((kb + kselB) ^ xmk));
#pragma unroll
                for (int mt = 0; mt < 2; mt++) {
                    mma_bf16(acc[mt][nt * 2],     ah[mt], bh[0], bh[1]);
                    mma_bf16(acc[mt][nt * 2 + 1], ah[mt], bh[2], bh[3]);
                    mma_bf16(acc[mt][nt * 2],     al[mt], bh[0], bh[1]);
                    mma_bf16(acc[mt][nt * 2 + 1], al[mt], bh[2], bh[3]);
                    mma_bf16(acc[mt][nt * 2],     ah[mt], bl[0], bl[1]);
                    mma_bf16(acc[mt][nt * 2 + 1], ah[mt], bl[2], bl[3]);
                }
            }
        }
    };

    issue(0, 0); cp_commit();
    issue(1, 1); cp_commit();
    for (int kt = 0; kt < 4; kt++) {
        if (kt == 3) cp_wait0(); else cp_wait1();
        __syncthreads();
        compute(kt & 1);
        if (kt + 2 < 4) {
            __syncthreads();
            issue(kt + 2, kt & 1);
            cp_commit();
        }
    }

    const int g = lane >> 2, t4 = lane & 3;
#pragma unroll
    for (int mt = 0; mt < 2; mt++)
#pragma unroll
        for (int n8 = 0; n8 < 4; n8++) {
            const float* c = acc[mt][n8];
            const int col = n0 + nw * 32 + n8 * 8 + 2 * t4;
            const int r0 = m0 + mw * 32 + mt * 16 + g;
            const size_t o0 = (size_t)r0 * DH + col;
            const size_t o1 = o0 + 8 * DH;
            float2 bi = *reinterpret_cast<const float2*>(b1 + col);
            *reinterpret_cast<float2*>(Z + o0) = make_float2(c[0] + bi.x, c[1] + bi.y);
            *reinterpret_cast<float2*>(Z + o1) = make_float2(c[2] + bi.x, c[3] + bi.y);
        }
}

// ---------------- packed f32x2 GEMM (readout only) ----------------
__device__ __forceinline__ void fma2(unsigned long long& acc,
                                     unsigned long long a, unsigned long long b) {
    asm("fma.rn.f32x2 %0, %1, %2, %0;" : "+l"(acc) : "l"(a), "l"(b));
}
__device__ __forceinline__ unsigned long long pack2(float x, float y) {
    unsigned long long r;
    asm("mov.b64 %0, {%1, %2};" : "=l"(r) : "f"(x), "f"(y));
    return r;
}
__device__ __forceinline__ float2 unpack2(unsigned long long v) {
    float2 f;
    asm("mov.b64 {%0, %1}, %2;" : "=f"(f.x), "=f"(f.y) : "l"(v));
    return f;
}

template <int BM, int BN, int BK, int TM>
__global__ void __launch_bounds__(256)
gemm_f32x2(const float* __restrict__ A, const float* __restrict__ Bm,
           const float* __restrict__ aux, float* __restrict__ C,
           int M, int N, int K) {
    constexpr int TN = 4;
    constexpr int NT = (BM / TM) * (BN / TN);
    static_assert(NT == 256, "block must be 256 threads");
    __shared__ float As[BK][BM + 4];
    __shared__ float Bs[BK][BN];

    const int tid = threadIdx.x;
    const int n0 = blockIdx.x * BN;
    const int m0 = blockIdx.y * BM;
    constexpr int A_PER = (BM * BK / 4) / NT;
    constexpr int B_PER = (BK * BN / 4) / NT;
    float4 ar[A_PER], br[B_PER];

    auto loadA = [&](int kt) {
#pragma unroll
        for (int i = 0; i < A_PER; i++) {
            int idx = tid + i * NT, row = idx / (BK / 4), kc = idx % (BK / 4);
            ar[i] = *reinterpret_cast<const float4*>(&A[(size_t)(m0 + row) * K + kt * BK + kc * 4]);
        }
    };
    auto storeA = [&]() {
#pragma unroll
        for (int i = 0; i < A_PER; i++) {
            int idx = tid + i * NT, row = idx / (BK / 4), kc = idx % (BK / 4);
            As[kc * 4 + 0][row] = ar[i].x; As[kc * 4 + 1][row] = ar[i].y;
            As[kc * 4 + 2][row] = ar[i].z; As[kc * 4 + 3][row] = ar[i].w;
        }
    };
    auto loadB = [&](int kt) {
#pragma unroll
        for (int i = 0; i < B_PER; i++) {
            int idx = tid + i * NT, kr = idx / (BN / 4), nc = idx % (BN / 4);
            br[i] = *reinterpret_cast<const float4*>(&Bm[(size_t)(kt * BK + kr) * N + n0 + nc * 4]);
        }
    };
    auto storeB = [&]() {
#pragma unroll
        for (int i = 0; i < B_PER; i++) {
            int idx = tid + i * NT, kr = idx / (BN / 4), nc = idx % (BN / 4);
            *reinterpret_cast<float4*>(&Bs[kr][nc * 4]) = br[i];
        }
    };

    unsigned long long acc[TM][2];
#pragma unroll
    for (int i = 0; i < TM; i++) { acc[i][0] = pack2(0, 0); acc[i][1] = pack2(0, 0); }

    const int rg = tid / (BN / TN), cg = tid % (BN / TN);
    const int r0 = rg * TM, c0 = cg * TN;
    const int nk = K / BK;
    loadA(0); loadB(0); storeA(); storeB();
    __syncthreads();
    for (int kt = 0; kt < nk; kt++) {
        if (kt + 1 < nk) { loadA(kt + 1); loadB(kt + 1); }
#pragma unroll
        for (int k = 0; k < BK; k++) {
            float a[TM];
            if (TM == 2) {
                float2 avv = *reinterpret_cast<const float2*>(&As[k][r0]);
                a[0] = avv.x; a[1] = avv.y;
            } else {
                float4 avv = *reinterpret_cast<const float4*>(&As[k][r0]);
                a[0] = avv.x; a[1] = avv.y; a[2] = avv.z; a[3] = avv.w;
            }
            float4 bvv = *reinterpret_cast<const float4*>(&Bs[k][c0]);
            unsigned long long b01 = pack2(bvv.x, bvv.y), b23 = pack2(bvv.z, bvv.w);
#pragma unroll
            for (int i = 0; i < TM; i++) {
                unsigned long long aa = pack2(a[i], a[i]);
                fma2(acc[i][0], aa, b01);
                fma2(acc[i][1], aa, b23);
            }
        }
        __syncthreads();
        if (kt + 1 < nk) { storeA(); storeB(); __syncthreads(); }
    }
#pragma unroll
    for (int i = 0; i < TM; i++) {
        float2 p0 = unpack2(acc[i][0]), p1 = unpack2(acc[i][1]);
        float4 v = make_float4(p0.x, p0.y, p1.x, p1.y);
        const int row = m0 + r0 + i, col = n0 + c0;
        const size_t off = (size_t)row * N + col;
        float s = aux[0];
        v.x += s; v.y += s; v.z += s; v.w += s;
        *reinterpret_cast<float4*>(&C[off]) = v;
    }
}

// ---------------- host launcher ----------------
extern "C" void kernel_launch(void* const* d_in, const int* in_sizes, int n_in,
                              void* d_out, int out_size) {
    const float* xs  = (const float*)d_in[0];
    const float* W1x = (const float*)d_in[1];
    const float* W1h = (const float*)d_in[2];
    const float* b1  = (const float*)d_in[3];
    const float* W2  = (const float*)d_in[4];
    const float* b2  = (const float*)d_in[5];
    float* out = (float*)d_out;

    float *zp, *hf;
    int* barp;
    __nv_bfloat16 *hhi, *hlo, *wthi, *wtlo, *xshi, *xslo, *wxhi, *wxlo;
    cudaGetSymbolAddress((void**)&zp, g_z);
    cudaGetSymbolAddress((void**)&hf, g_hf);
    cudaGetSymbolAddress((void**)&hhi, g_h_hi);
    cudaGetSymbolAddress((void**)&hlo, g_h_lo);
    cudaGetSymbolAddress((void**)&wthi, g_wt_hi);
    cudaGetSymbolAddress((void**)&wtlo, g_wt_lo);
    cudaGetSymbolAddress((void**)&xshi, g_xs_hi);
    cudaGetSymbolAddress((void**)&xslo, g_xs_lo);
    cudaGetSymbolAddress((void**)&wxhi, g_w1xt_hi);
    cudaGetSymbolAddress((void**)&wxlo, g_w1xt_lo);
    cudaGetSymbolAddress((void**)&barp, g_bar);

    cudaFuncSetAttribute(pre_hmma, cudaFuncAttributeMaxDynamicSharedMemorySize, 2 * PST_SZ);
    cudaFuncSetAttribute(rnn_persist, cudaFuncAttributeMaxDynamicSharedMemorySize, SMEM_TOT);

    const int XN = T_STEPS * BATCH * DIN;

    // splits
    fsplit_kernel<<<XN / 4 / 256, 256>>>(xs, xshi, xslo, XN / 4);
    wsplit_kernel<<<dim3(DH / 32, DIN / 32), dim3(32, 8)>>>(W1x, wxhi, wxlo, DIN, DH);
    wsplit_kernel<<<dim3(DH / 32, DH / 32), dim3(32, 8)>>>(W1h, wthi, wtlo, DH, DH);

    // zero barrier slots
    zero_u4<<<16, 256>>>((uint4*)barp, T_STEPS * 4 * 32 / 4);

    // Z = xs@W1x + b1 (HMMA, per-tile 3-term)
    pre_hmma<<<dim3(16, 256), 256, 2 * PST_SZ>>>(xshi, xslo, wxhi, wxlo, b1, zp);

    // full recurrence in one persistent launch (W resident, per-mg barrier)
    rnn_persist<<<128, 256, SMEM_TOT>>>(hhi, hlo, wthi, wtlo, zp, hf, barp);

    // out = h_final @ W2 + b2
    gemm_f32x2<32, 64, 32, 2>
        <<<dim3(DOUT / 64, BATCH / 32), 256>>>(hf, W2, b2, out, BATCH, DOUT, DH);
}

// round 15
// speedup vs baseline: 1.2430x; 1.0105x over previous
#include <cuda_runtime.h>
#include <cuda_bf16.h>
#include <math.h>
#include <stdint.h>

#define T_STEPS 128
#define BATCH   256
#define DIN     256
#define DH      1024
#define DOUT    256

// ---------------- device scratch ----------------
__device__ float g_z[(size_t)T_STEPS * BATCH * DH];          // 134 MB: xs@W1x + b1
__device__ float g_hf[(size_t)BATCH * DH];                   // fp32 h (final step only)
__device__ __nv_bfloat16 g_h_hi[2][(size_t)BATCH * DH];      // ping-pong split h
__device__ __nv_bfloat16 g_h_lo[2][(size_t)BATCH * DH];
__device__ __nv_bfloat16 g_wt_hi[(size_t)DH * DH];           // W1h^T split: wt[n][k]
__device__ __nv_bfloat16 g_wt_lo[(size_t)DH * DH];
__device__ __nv_bfloat16 g_xs_hi[(size_t)T_STEPS * BATCH * DIN];  // xs split
__device__ __nv_bfloat16 g_xs_lo[(size_t)T_STEPS * BATCH * DIN];
__device__ __nv_bfloat16 g_w1xt_hi[(size_t)DH * DIN];        // W1x^T split
__device__ __nv_bfloat16 g_w1xt_lo[(size_t)DH * DIN];
// per-(step, m-group) barrier slots, each padded to 128B (own L2 line)
__device__ int g_bar[T_STEPS * 4 * 32];

// ---------------- helpers ----------------
__device__ __forceinline__ uint32_t smem_u32(const void* p) {
    uint32_t a;
    asm("{ .reg .u64 t; cvta.to.shared.u64 t, %1; cvt.u32.u64 %0, t; }" : "=r"(a) : "l"(p));
    return a;
}
__device__ __forceinline__ void cp_async16(uint32_t dst, const void* src) {
    asm volatile("cp.async.cg.shared.global [%0], [%1], 16;" :: "r"(dst), "l"(src) : "memory");
}
__device__ __forceinline__ void cp_commit() {
    asm volatile("cp.async.commit_group;" ::: "memory");
}
__device__ __forceinline__ void cp_wait1() {
    asm volatile("cp.async.wait_group 1;" ::: "memory");
}
__device__ __forceinline__ void cp_wait0() {
    asm volatile("cp.async.wait_group 0;" ::: "memory");
}
__device__ __forceinline__ void ldmatrix_x4(uint32_t* r, uint32_t addr) {
    asm volatile("ldmatrix.sync.aligned.m8n8.x4.shared.b16 {%0,%1,%2,%3}, [%4];"
                 : "=r"(r[0]), "=r"(r[1]), "=r"(r[2]), "=r"(r[3]) : "r"(addr));
}
__device__ __forceinline__ void mma_bf16(float* c, const uint32_t* a,
                                         uint32_t b0, uint32_t b1) {
    asm volatile(
        "mma.sync.aligned.m16n8k16.row.col.f32.bf16.bf16.f32 "
        "{%0,%1,%2,%3},{%4,%5,%6,%7},{%8,%9},{%0,%1,%2,%3};"
        : "+f"(c[0]), "+f"(c[1]), "+f"(c[2]), "+f"(c[3])
        : "r"(a[0]), "r"(a[1]), "r"(a[2]), "r"(a[3]), "r"(b0), "r"(b1));
}
__device__ __forceinline__ float tanh_fast(float x) {
    float ax = fabsf(x);
    float e;
    asm("ex2.approx.f32 %0, %1;" : "=f"(e) : "f"(ax * -2.885390081777927f)); // e^{-2|x|}
    float r = __fdividef(1.0f - e, 1.0f + e);
    return __uint_as_float(__float_as_uint(r) | (__float_as_uint(x) & 0x80000000u));
}
__device__ __forceinline__ uint32_t prmt_hi(uint32_t x, uint32_t y) {
    uint32_t d;
    asm("prmt.b32 %0, %1, %2, 0x7632;" : "=r"(d) : "r"(x), "r"(y));
    return d;
}
__device__ __forceinline__ uint32_t cvt_bf16x2(float hi, float lo) {
    uint32_t d;
    asm("cvt.rn.bf16x2.f32 %0, %1, %2;" : "=r"(d) : "f"(hi), "f"(lo));
    return d;
}

// ---------------- utility kernels ----------------
__global__ void zero_u4(uint4* __restrict__ p, int n4) {
    int i = blockIdx.x * blockDim.x + threadIdx.x;
    if (i < n4) p[i] = make_uint4(0, 0, 0, 0);
}

__global__ void fsplit_kernel(const float* __restrict__ in,
                              __nv_bfloat16* __restrict__ hi,
                              __nv_bfloat16* __restrict__ lo, int n4) {
    int i = blockIdx.x * blockDim.x + threadIdx.x;
    if (i >= n4) return;
    float4 v = reinterpret_cast<const float4*>(in)[i];
    uint32_t u0 = __float_as_uint(v.x), u1 = __float_as_uint(v.y);
    uint32_t u2 = __float_as_uint(v.z), u3 = __float_as_uint(v.w);
    reinterpret_cast<uint2*>(hi)[i] = make_uint2(prmt_hi(u0, u1), prmt_hi(u2, u3));
    float l0 = v.x - __uint_as_float(u0 & 0xFFFF0000u);
    float l1 = v.y - __uint_as_float(u1 & 0xFFFF0000u);
    float l2 = v.z - __uint_as_float(u2 & 0xFFFF0000u);
    float l3 = v.w - __uint_as_float(u3 & 0xFFFF0000u);
    reinterpret_cast<uint2*>(lo)[i] = make_uint2(cvt_bf16x2(l1, l0), cvt_bf16x2(l3, l2));
}

// transpose + bf16 split: W[k][n] (KxN) -> out[n][k]
__global__ void wsplit_kernel(const float* __restrict__ W,
                              __nv_bfloat16* __restrict__ hi,
                              __nv_bfloat16* __restrict__ lo, int K, int N) {
    __shared__ float t[32][33];
    const int tx = threadIdx.x, ty = threadIdx.y;
    const int kb = blockIdx.y * 32, nb = blockIdx.x * 32;
#pragma unroll
    for (int i = 0; i < 32; i += 8)
        t[ty + i][tx] = W[(size_t)(kb + ty + i) * N + nb + tx];
    __syncthreads();
#pragma unroll
    for (int i = 0; i < 32; i += 8) {
        const int n = nb + ty + i, k = kb + tx;
        float v = t[tx][ty + i];
        __nv_bfloat16 h = __float2bfloat16(v);
        hi[(size_t)n * K + k] = h;
        lo[(size_t)n * K + k] = __float2bfloat16(v - __bfloat162float(h));
    }
}

// =====================================================================
// Persistent recurrence kernel, W resident in smem; W_hi fragments
// additionally RESIDENT IN REGISTERS (64 regs/warp, loaded once).
// grid 128 CTAs x 256 threads; CTA c: n0=(c&31)*32, m0=(c>>5)*64.
// 8 warps split-K (warp w owns k16 slice w of each 128-k tile).
// Step 0 skips the GEMM entirely; Z prefetched before the barrier.
// =====================================================================
#define W_HI_OFF  0
#define W_LO_OFF  65536
#define ST_OFF    131072
#define ST_SZ     32768
#define SMEM_TOT  229376
#define RP 36
#define WBP 2308

__global__ void __launch_bounds__(256, 1)
rnn_persist(const __nv_bfloat16* __restrict__ hhi0, const __nv_bfloat16* __restrict__ hlo0,
            const __nv_bfloat16* __restrict__ wt_hi, const __nv_bfloat16* __restrict__ wt_lo,
            const float* __restrict__ Z, float* __restrict__ o_f,
            int* __restrict__ bar) {
    extern __shared__ __align__(128) char sm[];
    const uint32_t sb = smem_u32(sm);

    const int tid = threadIdx.x;
    const int w = tid >> 5;
    const int lane = tid & 31;
    const int cta = blockIdx.x;
    const int n0 = (cta & 31) * 32;
    const int m0 = (cta >> 5) * 64;
    const int mg = cta >> 5;
    const size_t HS = (size_t)BATCH * DH;

    // ---- load W slice into smem once ----
    {
#pragma unroll
        for (int i = 0; i < 16; i++) {
            const int c = tid + i * 256;
            const int row = c >> 7, u = c & 127;
            cp_async16(sb + W_HI_OFF + row * 2048 + ((u * 16) ^ ((row & 7) << 4)),
                       wt_hi + (size_t)(n0 + row) * DH + u * 8);
        }
#pragma unroll
        for (int i = 0; i < 16; i++) {
            const int c = tid + i * 256;
            const int row = c >> 7, u = c & 127;
            cp_async16(sb + W_LO_OFF + row * 2048 + ((u * 16) ^ ((row & 7) << 4)),
                       wt_lo + (size_t)(n0 + row) * DH + u * 8);
        }
        cp_commit();
    }

    // consumer addressing (constant across steps)
    const int l7 = lane & 7;
    const uint32_t xmk = (uint32_t)(l7 << 4);
    const int rowA = ((lane >> 3) & 1) * 8 + l7;
    const uint32_t kselA = ((lane >> 4) & 1) * 16;
    const int rowBb = ((lane >> 4) & 1) * 8 + l7;
    const uint32_t kselB = ((lane >> 3) & 1) * 16;
    const uint32_t wkb = (uint32_t)(w * 32);

    // epilogue addressing (constant)
    const int erow = tid >> 2;
    const int ec0 = (tid & 3) * 8;
    const size_t eoff = (size_t)(m0 + erow) * DH + n0 + ec0;

    // ---- W_hi fragments resident in registers (loaded once) ----
    cp_wait0();
    __syncthreads();
    uint32_t bhr[8][2][4];
#pragma unroll
    for (int kt = 0; kt < 8; kt++)
#pragma unroll
        for (int nt = 0; nt < 2; nt++)
            ldmatrix_x4(bhr[kt][nt],
                        sb + W_HI_OFF + (nt * 16 + rowBb) * 2048 +
                            (((uint32_t)(kt << 8) + wkb + kselB) ^ xmk));

    // Z prefetch for step 0
    float4 zpre0 = *reinterpret_cast<const float4*>(Z + eoff);
    float4 zpre1 = *reinterpret_cast<const float4*>(Z + eoff + 4);

    for (int t = 0; t < T_STEPS; t++) {
        const int cur = t & 1;
        const __nv_bfloat16* h_hi = hhi0 + cur * HS;
        const __nv_bfloat16* h_lo = hlo0 + cur * HS;
        __nv_bfloat16* o_hi = const_cast<__nv_bfloat16*>(hhi0) + (cur ^ 1) * HS;
        __nv_bfloat16* o_lo = const_cast<__nv_bfloat16*>(hlo0) + (cur ^ 1) * HS;

        auto issue = [&](int kt, int buf) {
            const int k0 = kt << 7;
            const uint32_t st = sb + ST_OFF + buf * ST_SZ;
#pragma unroll
            for (int i = 0; i < 4; i++) {           // A_hi: 64 rows x 256B
                const int c = tid + (i << 8);
                const int row = c >> 4, u = c & 15;
                cp_async16(st + row * 256 + ((u * 16) ^ ((row & 7) << 4)),
                           h_hi + (size_t)(m0 + row) * DH + k0 + u * 8);
            }
#pragma unroll
            for (int i = 0; i < 4; i++) {           // A_lo
                const int c = tid + (i << 8);
                const int row = c >> 4, u = c & 15;
                cp_async16(st + 16384 + row * 256 + ((u * 16) ^ ((row & 7) << 4)),
                           h_lo + (size_t)(m0 + row) * DH + k0 + u * 8);
            }
        };

        float acc[4][4][4];
#pragma unroll
        for (int mt = 0; mt < 4; mt++)
#pragma unroll
            for (int n8 = 0; n8 < 4; n8++)
#pragma unroll
                for (int q = 0; q < 4; q++) acc[mt][n8][q] = 0.0f;

        auto compute = [&](int kt, int buf) {
            const uint32_t aHi = sb + ST_OFF + buf * ST_SZ;
            const uint32_t aLo = aHi + 16384;
            const uint32_t tkb = (uint32_t)(kt << 8);
            uint32_t ah[4][4], al[4][4], bl[2][4];
#pragma unroll
            for (int mt = 0; mt < 4; mt++) {
                ldmatrix_x4(ah[mt], aHi + (mt * 16 + rowA) * 256 + ((wkb + kselA) ^ xmk));
                ldmatrix_x4(al[mt], aLo + (mt * 16 + rowA) * 256 + ((wkb + kselA) ^ xmk));
            }
#pragma unroll
            for (int nt = 0; nt < 2; nt++)
                ldmatrix_x4(bl[nt], sb + W_LO_OFF + (nt * 16 + rowBb) * 2048 +
                                        ((tkb + wkb + kselB) ^ xmk));
#pragma unroll
            for (int mt = 0; mt < 4; mt++)
#pragma unroll
                for (int nt = 0; nt < 2; nt++) {
                    mma_bf16(acc[mt][nt * 2],     ah[mt], bhr[kt][nt][0], bhr[kt][nt][1]);
                    mma_bf16(acc[mt][nt * 2 + 1], ah[mt], bhr[kt][nt][2], bhr[kt][nt][3]);
                    mma_bf16(acc[mt][nt * 2],     al[mt], bhr[kt][nt][0], bhr[kt][nt][1]);
                    mma_bf16(acc[mt][nt * 2 + 1], al[mt], bhr[kt][nt][2], bhr[kt][nt][3]);
                    mma_bf16(acc[mt][nt * 2],     ah[mt], bl[nt][0], bl[nt][1]);
                    mma_bf16(acc[mt][nt * 2 + 1], ah[mt], bl[nt][2], bl[nt][3]);
                }
        };

        float* sred = reinterpret_cast<float*>(sm + ST_OFF);

        if (t > 0) {
            issue(0, 0); cp_commit();
            issue(1, 1); cp_commit();

            for (int kt = 0; kt < 8; kt++) {
                cp_wait1();
                __syncthreads();
                if (kt + 2 < 8) issue(kt + 2, (kt + 2) % 3);
                cp_commit();
                compute(kt, kt % 3);
            }

            // ---- cross-warp split-K reduction through smem ----
            cp_wait0();
            __syncthreads();
            float* ms = sred + w * WBP;
            const int g = lane >> 2, t4 = lane & 3;
#pragma unroll
            for (int mt = 0; mt < 4; mt++)
#pragma unroll
                for (int n8 = 0; n8 < 4; n8++) {
                    const int r0 = mt * 16 + g, c = n8 * 8 + 2 * t4;
                    *reinterpret_cast<float2*>(&ms[r0 * RP + c]) =
                        make_float2(acc[mt][n8][0], acc[mt][n8][1]);
                    *reinterpret_cast<float2*>(&ms[(r0 + 8) * RP + c]) =
                        make_float2(acc[mt][n8][2], acc[mt][n8][3]);
                }
            __syncthreads();
        }

        // ---- fused epilogue: sum 8 partials + Z, tanh, store splits ----
#pragma unroll
        for (int q = 0; q < 2; q++) {
            const int col = ec0 + q * 4;
            float4 s = make_float4(0.0f, 0.0f, 0.0f, 0.0f);
            if (t > 0) {
                s = *reinterpret_cast<const float4*>(&sred[erow * RP + col]);
#pragma unroll
                for (int w2 = 1; w2 < 8; w2++) {
                    float4 p = *reinterpret_cast<const float4*>(
                        &sred[w2 * WBP + erow * RP + col]);
                    s.x += p.x; s.y += p.y; s.z += p.z; s.w += p.w;
                }
            }
            const size_t off = eoff + q * 4;
            const float4 z = q ? zpre1 : zpre0;
            float v0 = tanh_fast(s.x + z.x);
            float v1 = tanh_fast(s.y + z.y);
            float v2 = tanh_fast(s.z + z.z);
            float v3 = tanh_fast(s.w + z.w);
            if (t == T_STEPS - 1)
                *reinterpret_cast<float4*>(o_f + off) = make_float4(v0, v1, v2, v3);
            uint32_t u0 = __float_as_uint(v0), u1 = __float_as_uint(v1);
            uint32_t u2 = __float_as_uint(v2), u3 = __float_as_uint(v3);
            *reinterpret_cast<uint2*>(o_hi + off) = make_uint2(prmt_hi(u0, u1), prmt_hi(u2, u3));
            float l0 = v0 - __uint_as_float(u0 & 0xFFFF0000u);
            float l1 = v1 - __uint_as_float(u1 & 0xFFFF0000u);
            float l2 = v2 - __uint_as_float(u2 & 0xFFFF0000u);
            float l3 = v3 - __uint_as_float(u3 & 0xFFFF0000u);
            *reinterpret_cast<uint2*>(o_lo + off) = make_uint2(cvt_bf16x2(l1, l0), cvt_bf16x2(l3, l2));
        }

        // ---- prefetch next step's Z, then per-m-group barrier ----
        if (t < T_STEPS - 1) {
            const float* Zn = Z + (size_t)(t + 1) * HS;
            float4 znx0 = *reinterpret_cast<const float4*>(Zn + eoff);
            float4 znx1 = *reinterpret_cast<const float4*>(Zn + eoff + 4);
            __syncthreads();
            if (tid == 0) {
                int* slot = bar + (t * 4 + mg) * 32;
                asm volatile("red.release.gpu.global.add.s32 [%0], 1;" :: "l"(slot) : "memory");
                int v;
                do {
                    __nanosleep(16);
                    asm volatile("ld.acquire.gpu.global.b32 %0, [%1];" : "=r"(v) : "l"(slot) : "memory");
                } while (v < 32);
            }
            __syncthreads();
            zpre0 = znx0;
            zpre1 = znx1;
        }
    }
}

// =====================================================================
// Precompute kernel v3: Z = xs @ W1x + b1, fp32 via per-tile 3-term.
// CTA 128(M) x 64(N), grid (16, 256), 8 warps = 4m x 2n, occ 2.
// =====================================================================
#define PST_SZ 49152

__global__ void __launch_bounds__(256, 2)
pre_hmma(const __nv_bfloat16* __restrict__ xs_hi, const __nv_bfloat16* __restrict__ xs_lo,
         const __nv_bfloat16* __restrict__ wx_hi, const __nv_bfloat16* __restrict__ wx_lo,
         const float* __restrict__ b1, float* __restrict__ Z) {
    extern __shared__ __align__(128) char pool[];   // 2 x 48KB stages

    const int tid = threadIdx.x;
    const int w = tid >> 5;
    const int lane = tid & 31;
    const int mw = w & 3, nw = w >> 2;
    const int n0 = blockIdx.x * 64;
    const int m0 = blockIdx.y * 128;
    const uint32_t base = smem_u32(pool);

    auto issue = [&](int kt, int buf) {
        const int k0 = kt << 6;
        const uint32_t st = base + buf * PST_SZ;
#pragma unroll
        for (int i = 0; i < 4; i++) {               // A_hi: 128 rows x 128B
            const int c = tid + (i << 8);
            const int row = c >> 3, u = c & 7;
            cp_async16(st + row * 128 + ((u * 16) ^ ((row & 7) << 4)),
                       xs_hi + (size_t)(m0 + row) * DIN + k0 + u * 8);
        }
#pragma unroll
        for (int i = 0; i < 4; i++) {               // A_lo
            const int c = tid + (i << 8);
            const int row = c >> 3, u = c & 7;
            cp_async16(st + 16384 + row * 128 + ((u * 16) ^ ((row & 7) << 4)),
                       xs_lo + (size_t)(m0 + row) * DIN + k0 + u * 8);
        }
#pragma unroll
        for (int i = 0; i < 2; i++) {               // B_hi: 64 rows x 128B
            const int c = tid + (i << 8);
            const int row = c >> 3, u = c & 7;
            cp_async16(st + 32768 + row * 128 + ((u * 16) ^ ((row & 7) << 4)),
                       wx_hi + (size_t)(n0 + row) * DIN + k0 + u * 8);
        }
#pragma unroll
        for (int i = 0; i < 2; i++) {               // B_lo
            const int c = tid + (i << 8);
            const int row = c >> 3, u = c & 7;
            cp_async16(st + 40960 + row * 128 + ((u * 16) ^ ((row & 7) << 4)),
                       wx_lo + (size_t)(n0 + row) * DIN + k0 + u * 8);
        }
    };

    const int l7 = lane & 7;
    const uint32_t xmk = (uint32_t)(l7 << 4);
    const int rowA = ((lane >> 3) & 1) * 8 + l7;
    const uint32_t kselA = ((lane >> 4) & 1) * 16;
    const int rowBb = ((lane >> 4) & 1) * 8 + l7;
    const uint32_t kselB = ((lane >> 3) & 1) * 16;

    float acc[2][4][4];
#pragma unroll
    for (int mt = 0; mt < 2; mt++)
#pragma unroll
        for (int n8 = 0; n8 < 4; n8++)
#pragma unroll
            for (int q = 0; q < 4; q++) acc[mt][n8][q] = 0.0f;

    auto compute = [&](int buf) {
        const uint32_t st = base + buf * PST_SZ;
        const uint32_t aHi = st, aLo = st + 16384;
        const uint32_t bHi = st + 32768, bLo = st + 40960;
#pragma unroll
        for (int k16 = 0; k16 < 4; k16++) {
            const uint32_t kb = (uint32_t)(k16 * 32);
            uint32_t ah[2][4], al[2][4];
#pragma unroll
            for (int mt = 0; mt < 2; mt++) {
                ldmatrix_x4(ah[mt], aHi + (mw * 32 + mt * 16 + rowA) * 128 + ((kb + kselA) ^ xmk));
                ldmatrix_x4(al[mt], aLo + (mw * 32 + mt * 16 + rowA) * 128 + ((kb + kselA) ^ xmk));
            }
#pragma unroll
            for (int nt = 0; nt < 2; nt++) {
                uint32_t bh[4], bl[4];
                ldmatrix_x4(bh, bHi + (nw * 32 + nt * 16 + rowBb) * 128 + ((kb + kselB) ^ xmk));
                ldmatrix_x4(bl, bLo + (nw * 32 + nt * 16 + rowBb) * 128 + ((kb + kselB) ^ xmk));
#pragma unroll
                for (int mt = 0; mt < 2; mt++) {
                    mma_bf16(acc[mt][nt * 2],     ah[mt], bh[0], bh[1]);
                    mma_bf16(acc[mt][nt * 2 + 1], ah[mt], bh[2], bh[3]);
                    mma_bf16(acc[mt][nt * 2],     al[mt], bh[0], bh[1]);
                    mma_bf16(acc[mt][nt * 2 + 1], al[mt], bh[2], bh[3]);
                    mma_bf16(acc[mt][nt * 2],     ah[mt], bl[0], bl[1]);
                    mma_bf16(acc[mt][nt * 2 + 1], ah[mt], bl[2], bl[3]);
                }
            }
        }
    };

    issue(0, 0); cp_commit();
    issue(1, 1); cp_commit();
    for (int kt = 0; kt < 4; kt++) {
        if (kt == 3) cp_wait0(); else cp_wait1();
        __syncthreads();
        compute(kt & 1);
        if (kt + 2 < 4) {
            __syncthreads();
            issue(kt + 2, kt & 1);
            cp_commit();
        }
    }

    const int g = lane >> 2, t4 = lane & 3;
#pragma unroll
    for (int mt = 0; mt < 2; mt++)
#pragma unroll
        for (int n8 = 0; n8 < 4; n8++) {
            const float* c = acc[mt][n8];
            const int col = n0 + nw * 32 + n8 * 8 + 2 * t4;
            const int r0 = m0 + mw * 32 + mt * 16 + g;
            const size_t o0 = (size_t)r0 * DH + col;
            const size_t o1 = o0 + 8 * DH;
            float2 bi = *reinterpret_cast<const float2*>(b1 + col);
            *reinterpret_cast<float2*>(Z + o0) = make_float2(c[0] + bi.x, c[1] + bi.y);
            *reinterpret_cast<float2*>(Z + o1) = make_float2(c[2] + bi.x, c[3] + bi.y);
        }
}

// ---------------- packed f32x2 GEMM (readout only) ----------------
__device__ __forceinline__ void fma2(unsigned long long& acc,
                                     unsigned long long a, unsigned long long b) {
    asm("fma.rn.f32x2 %0, %1, %2, %0;" : "+l"(acc) : "l"(a), "l"(b));
}
__device__ __forceinline__ unsigned long long pack2(float x, float y) {
    unsigned long long r;
    asm("mov.b64 %0, {%1, %2};" : "=l"(r) : "f"(x), "f"(y));
    return r;
}
__device__ __forceinline__ float2 unpack2(unsigned long long v) {
    float2 f;
    asm("mov.b64 {%0, %1}, %2;" : "=f"(f.x), "=f"(f.y) : "l"(v));
    return f;
}

template <int BM, int BN, int BK, int TM>
__global__ void __launch_bounds__(256)
gemm_f32x2(const float* __restrict__ A, const float* __restrict__ Bm,
           const float* __restrict__ aux, float* __restrict__ C,
           int M, int N, int K) {
    constexpr int TN = 4;
    constexpr int NT = (BM / TM) * (BN / TN);
    static_assert(NT == 256, "block must be 256 threads");
    __shared__ float As[BK][BM + 4];
    __shared__ float Bs[BK][BN];

    const int tid = threadIdx.x;
    const int n0 = blockIdx.x * BN;
    const int m0 = blockIdx.y * BM;
    constexpr int A_PER = (BM * BK / 4) / NT;
    constexpr int B_PER = (BK * BN / 4) / NT;
    float4 ar[A_PER], br[B_PER];

    auto loadA = [&](int kt) {
#pragma unroll
        for (int i = 0; i < A_PER; i++) {
            int idx = tid + i * NT, row = idx / (BK / 4), kc = idx % (BK / 4);
            ar[i] = *reinterpret_cast<const float4*>(&A[(size_t)(m0 + row) * K + kt * BK + kc * 4]);
        }
    };
    auto storeA = [&]() {
#pragma unroll
        for (int i = 0; i < A_PER; i++) {
            int idx = tid + i * NT, row = idx / (BK / 4), kc = idx % (BK / 4);
            As[kc * 4 + 0][row] = ar[i].x; As[kc * 4 + 1][row] = ar[i].y;
            As[kc * 4 + 2][row] = ar[i].z; As[kc * 4 + 3][row] = ar[i].w;
        }
    };
    auto loadB = [&](int kt) {
#pragma unroll
        for (int i = 0; i < B_PER; i++) {
            int idx = tid + i * NT, kr = idx / (BN / 4), nc = idx % (BN / 4);
            br[i] = *reinterpret_cast<const float4*>(&Bm[(size_t)(kt * BK + kr) * N + n0 + nc * 4]);
        }
    };
    auto storeB = [&]() {
#pragma unroll
        for (int i = 0; i < B_PER; i++) {
            int idx = tid + i * NT, kr = idx / (BN / 4), nc = idx % (BN / 4);
            *reinterpret_cast<float4*>(&Bs[kr][nc * 4]) = br[i];
        }
    };

    unsigned long long acc[TM][2];
#pragma unroll
    for (int i = 0; i < TM; i++) { acc[i][0] = pack2(0, 0); acc[i][1] = pack2(0, 0); }

    const int rg = tid / (BN / TN), cg = tid % (BN / TN);
    const int r0 = rg * TM, c0 = cg * TN;
    const int nk = K / BK;
    loadA(0); loadB(0); storeA(); storeB();
    __syncthreads();
    for (int kt = 0; kt < nk; kt++) {
        if (kt + 1 < nk) { loadA(kt + 1); loadB(kt + 1); }
#pragma unroll
        for (int k = 0; k < BK; k++) {
            float a[TM];
            if (TM == 2) {
                float2 avv = *reinterpret_cast<const float2*>(&As[k][r0]);
                a[0] = avv.x; a[1] = avv.y;
            } else {
                float4 avv = *reinterpret_cast<const float4*>(&As[k][r0]);
                a[0] = avv.x; a[1] = avv.y; a[2] = avv.z; a[3] = avv.w;
            }
            float4 bvv = *reinterpret_cast<const float4*>(&Bs[k][c0]);
            unsigned long long b01 = pack2(bvv.x, bvv.y), b23 = pack2(bvv.z, bvv.w);
#pragma unroll
            for (int i = 0; i < TM; i++) {
                unsigned long long aa = pack2(a[i], a[i]);
                fma2(acc[i][0], aa, b01);
                fma2(acc[i][1], aa, b23);
            }
        }
        __syncthreads();
        if (kt + 1 < nk) { storeA(); storeB(); __syncthreads(); }
    }
#pragma unroll
    for (int i = 0; i < TM; i++) {
        float2 p0 = unpack2(acc[i][0]), p1 = unpack2(acc[i][1]);
        float4 v = make_float4(p0.x, p0.y, p1.x, p1.y);
        const int row = m0 + r0 + i, col = n0 + c0;
        const size_t off = (size_t)row * N + col;
        float s = aux[0];
        v.x += s; v.y += s; v.z += s; v.w += s;
        *reinterpret_cast<float4*>(&C[off]) = v;
    }
}

// ---------------- host launcher ----------------
extern "C" void kernel_launch(void* const* d_in, const int* in_sizes, int n_in,
                              void* d_out, int out_size) {
    const float* xs  = (const float*)d_in[0];
    const float* W1x = (const float*)d_in[1];
    const float* W1h = (const float*)d_in[2];
    const float* b1  = (const float*)d_in[3];
    const float* W2  = (const float*)d_in[4];
    const float* b2  = (const float*)d_in[5];
    float* out = (float*)d_out;

    float *zp, *hf;
    int* barp;
    __nv_bfloat16 *hhi, *hlo, *wthi, *wtlo, *xshi, *xslo, *wxhi, *wxlo;
    cudaGetSymbolAddress((void**)&zp, g_z);
    cudaGetSymbolAddress((void**)&hf, g_hf);
    cudaGetSymbolAddress((void**)&hhi, g_h_hi);
    cudaGetSymbolAddress((void**)&hlo, g_h_lo);
    cudaGetSymbolAddress((void**)&wthi, g_wt_hi);
    cudaGetSymbolAddress((void**)&wtlo, g_wt_lo);
    cudaGetSymbolAddress((void**)&xshi, g_xs_hi);
    cudaGetSymbolAddress((void**)&xslo, g_xs_lo);
    cudaGetSymbolAddress((void**)&wxhi, g_w1xt_hi);
    cudaGetSymbolAddress((void**)&wxlo, g_w1xt_lo);
    cudaGetSymbolAddress((void**)&barp, g_bar);

    cudaFuncSetAttribute(pre_hmma, cudaFuncAttributeMaxDynamicSharedMemorySize, 2 * PST_SZ);
    cudaFuncSetAttribute(rnn_persist, cudaFuncAttributeMaxDynamicSharedMemorySize, SMEM_TOT);

    const int XN = T_STEPS * BATCH * DIN;

    // splits
    fsplit_kernel<<<XN / 4 / 256, 256>>>(xs, xshi, xslo, XN / 4);
    wsplit_kernel<<<dim3(DH / 32, DIN / 32), dim3(32, 8)>>>(W1x, wxhi, wxlo, DIN, DH);
    wsplit_kernel<<<dim3(DH / 32, DH / 32), dim3(32, 8)>>>(W1h, wthi, wtlo, DH, DH);

    // zero barrier slots
    zero_u4<<<16, 256>>>((uint4*)barp, T_STEPS * 4 * 32 / 4);

    // Z = xs@W1x + b1 (HMMA, per-tile 3-term)
    pre_hmma<<<dim3(16, 256), 256, 2 * PST_SZ>>>(xshi, xslo, wxhi, wxlo, b1, zp);

    // full recurrence in one persistent launch (W resident, per-mg barrier)
    rnn_persist<<<128, 256, SMEM_TOT>>>(hhi, hlo, wthi, wtlo, zp, hf, barp);

    // out = h_final @ W2 + b2
    gemm_f32x2<32, 64, 32, 2>
        <<<dim3(DOUT / 64, BATCH / 32), 256>>>(hf, W2, b2, out, BATCH, DOUT, DH);
}

// round 16
// speedup vs baseline: 1.2616x; 1.0149x over previous
#include <cuda_runtime.h>
#include <cuda_bf16.h>
#include <math.h>
#include <stdint.h>

#define T_STEPS 128
#define BATCH   256
#define DIN     256
#define DH      1024
#define DOUT    256

// ---------------- device scratch ----------------
__device__ float g_z[(size_t)T_STEPS * BATCH * DH];          // 134 MB: xs@W1x + b1
__device__ float g_hf[(size_t)BATCH * DH];                   // (unused placeholder)
__device__ __nv_bfloat16 g_h_hi[2][(size_t)BATCH * DH];      // ping-pong split h
__device__ __nv_bfloat16 g_h_lo[2][(size_t)BATCH * DH];
__device__ __nv_bfloat16 g_wt_hi[(size_t)DH * DH];           // W1h^T split: wt[n][k]
__device__ __nv_bfloat16 g_wt_lo[(size_t)DH * DH];
__device__ __nv_bfloat16 g_xs_hi[(size_t)T_STEPS * BATCH * DIN];  // xs split
__device__ __nv_bfloat16 g_xs_lo[(size_t)T_STEPS * BATCH * DIN];
__device__ __nv_bfloat16 g_w1xt_hi[(size_t)DH * DIN];        // W1x^T split
__device__ __nv_bfloat16 g_w1xt_lo[(size_t)DH * DIN];
__device__ __nv_bfloat16 g_w2t_hi[(size_t)DOUT * DH];        // W2^T split [n=256][k=1024]
__device__ __nv_bfloat16 g_w2t_lo[(size_t)DOUT * DH];
// per-(step, m-group) barrier slots, each padded to 128B (own L2 line)
__device__ int g_bar[T_STEPS * 4 * 32];

// ---------------- helpers ----------------
__device__ __forceinline__ uint32_t smem_u32(const void* p) {
    uint32_t a;
    asm("{ .reg .u64 t; cvta.to.shared.u64 t, %1; cvt.u32.u64 %0, t; }" : "=r"(a) : "l"(p));
    return a;
}
__device__ __forceinline__ void cp_async16(uint32_t dst, const void* src) {
    asm volatile("cp.async.cg.shared.global [%0], [%1], 16;" :: "r"(dst), "l"(src) : "memory");
}
__device__ __forceinline__ void cp_commit() {
    asm volatile("cp.async.commit_group;" ::: "memory");
}
__device__ __forceinline__ void cp_wait1() {
    asm volatile("cp.async.wait_group 1;" ::: "memory");
}
__device__ __forceinline__ void cp_wait0() {
    asm volatile("cp.async.wait_group 0;" ::: "memory");
}
__device__ __forceinline__ void ldmatrix_x4(uint32_t* r, uint32_t addr) {
    asm volatile("ldmatrix.sync.aligned.m8n8.x4.shared.b16 {%0,%1,%2,%3}, [%4];"
                 : "=r"(r[0]), "=r"(r[1]), "=r"(r[2]), "=r"(r[3]) : "r"(addr));
}
__device__ __forceinline__ void mma_bf16(float* c, const uint32_t* a,
                                         uint32_t b0, uint32_t b1) {
    asm volatile(
        "mma.sync.aligned.m16n8k16.row.col.f32.bf16.bf16.f32 "
        "{%0,%1,%2,%3},{%4,%5,%6,%7},{%8,%9},{%0,%1,%2,%3};"
        : "+f"(c[0]), "+f"(c[1]), "+f"(c[2]), "+f"(c[3])
        : "r"(a[0]), "r"(a[1]), "r"(a[2]), "r"(a[3]), "r"(b0), "r"(b1));
}
__device__ __forceinline__ float tanh_fast(float x) {
    float ax = fabsf(x);
    float e;
    asm("ex2.approx.f32 %0, %1;" : "=f"(e) : "f"(ax * -2.885390081777927f)); // e^{-2|x|}
    float r = __fdividef(1.0f - e, 1.0f + e);
    return __uint_as_float(__float_as_uint(r) | (__float_as_uint(x) & 0x80000000u));
}
__device__ __forceinline__ uint32_t prmt_hi(uint32_t x, uint32_t y) {
    uint32_t d;
    asm("prmt.b32 %0, %1, %2, 0x7632;" : "=r"(d) : "r"(x), "r"(y));
    return d;
}
__device__ __forceinline__ uint32_t cvt_bf16x2(float hi, float lo) {
    uint32_t d;
    asm("cvt.rn.bf16x2.f32 %0, %1, %2;" : "=r"(d) : "f"(hi), "f"(lo));
    return d;
}

// ---------------- utility kernels ----------------
__global__ void zero_u4(uint4* __restrict__ p, int n4) {
    int i = blockIdx.x * blockDim.x + threadIdx.x;
    if (i < n4) p[i] = make_uint4(0, 0, 0, 0);
}

__global__ void fsplit_kernel(const float* __restrict__ in,
                              __nv_bfloat16* __restrict__ hi,
                              __nv_bfloat16* __restrict__ lo, int n4) {
    int i = blockIdx.x * blockDim.x + threadIdx.x;
    if (i >= n4) return;
    float4 v = reinterpret_cast<const float4*>(in)[i];
    uint32_t u0 = __float_as_uint(v.x), u1 = __float_as_uint(v.y);
    uint32_t u2 = __float_as_uint(v.z), u3 = __float_as_uint(v.w);
    reinterpret_cast<uint2*>(hi)[i] = make_uint2(prmt_hi(u0, u1), prmt_hi(u2, u3));
    float l0 = v.x - __uint_as_float(u0 & 0xFFFF0000u);
    float l1 = v.y - __uint_as_float(u1 & 0xFFFF0000u);
    float l2 = v.z - __uint_as_float(u2 & 0xFFFF0000u);
    float l3 = v.w - __uint_as_float(u3 & 0xFFFF0000u);
    reinterpret_cast<uint2*>(lo)[i] = make_uint2(cvt_bf16x2(l1, l0), cvt_bf16x2(l3, l2));
}

// transpose + bf16 split: W[k][n] (KxN) -> out[n][k]
__global__ void wsplit_kernel(const float* __restrict__ W,
                              __nv_bfloat16* __restrict__ hi,
                              __nv_bfloat16* __restrict__ lo, int K, int N) {
    __shared__ float t[32][33];
    const int tx = threadIdx.x, ty = threadIdx.y;
    const int kb = blockIdx.y * 32, nb = blockIdx.x * 32;
#pragma unroll
    for (int i = 0; i < 32; i += 8)
        t[ty + i][tx] = W[(size_t)(kb + ty + i) * N + nb + tx];
    __syncthreads();
#pragma unroll
    for (int i = 0; i < 32; i += 8) {
        const int n = nb + ty + i, k = kb + tx;
        float v = t[tx][ty + i];
        __nv_bfloat16 h = __float2bfloat16(v);
        hi[(size_t)n * K + k] = h;
        lo[(size_t)n * K + k] = __float2bfloat16(v - __bfloat162float(h));
    }
}

// =====================================================================
// Persistent recurrence kernel (R15, unchanged): W resident in smem,
// W_hi fragments resident in registers, split-K over 8 warps,
// Z prefetched before the per-m-group barrier. Step 0 skips the GEMM.
// =====================================================================
#define W_HI_OFF  0
#define W_LO_OFF  65536
#define ST_OFF    131072
#define ST_SZ     32768
#define SMEM_TOT  229376
#define RP 36
#define WBP 2308

__global__ void __launch_bounds__(256, 1)
rnn_persist(const __nv_bfloat16* __restrict__ hhi0, const __nv_bfloat16* __restrict__ hlo0,
            const __nv_bfloat16* __restrict__ wt_hi, const __nv_bfloat16* __restrict__ wt_lo,
            const float* __restrict__ Z, int* __restrict__ bar) {
    extern __shared__ __align__(128) char sm[];
    const uint32_t sb = smem_u32(sm);

    const int tid = threadIdx.x;
    const int w = tid >> 5;
    const int lane = tid & 31;
    const int cta = blockIdx.x;
    const int n0 = (cta & 31) * 32;
    const int m0 = (cta >> 5) * 64;
    const int mg = cta >> 5;
    const size_t HS = (size_t)BATCH * DH;

    // ---- load W slice into smem once ----
    {
#pragma unroll
        for (int i = 0; i < 16; i++) {
            const int c = tid + i * 256;
            const int row = c >> 7, u = c & 127;
            cp_async16(sb + W_HI_OFF + row * 2048 + ((u * 16) ^ ((row & 7) << 4)),
                       wt_hi + (size_t)(n0 + row) * DH + u * 8);
        }
#pragma unroll
        for (int i = 0; i < 16; i++) {
            const int c = tid + i * 256;
            const int row = c >> 7, u = c & 127;
            cp_async16(sb + W_LO_OFF + row * 2048 + ((u * 16) ^ ((row & 7) << 4)),
                       wt_lo + (size_t)(n0 + row) * DH + u * 8);
        }
        cp_commit();
    }

    // consumer addressing (constant across steps)
    const int l7 = lane & 7;
    const uint32_t xmk = (uint32_t)(l7 << 4);
    const int rowA = ((lane >> 3) & 1) * 8 + l7;
    const uint32_t kselA = ((lane >> 4) & 1) * 16;
    const int rowBb = ((lane >> 4) & 1) * 8 + l7;
    const uint32_t kselB = ((lane >> 3) & 1) * 16;
    const uint32_t wkb = (uint32_t)(w * 32);

    // epilogue addressing (constant)
    const int erow = tid >> 2;
    const int ec0 = (tid & 3) * 8;
    const size_t eoff = (size_t)(m0 + erow) * DH + n0 + ec0;

    // ---- W_hi fragments resident in registers (loaded once) ----
    cp_wait0();
    __syncthreads();
    uint32_t bhr[8][2][4];
#pragma unroll
    for (int kt = 0; kt < 8; kt++)
#pragma unroll
        for (int nt = 0; nt < 2; nt++)
            ldmatrix_x4(bhr[kt][nt],
                        sb + W_HI_OFF + (nt * 16 + rowBb) * 2048 +
                            (((uint32_t)(kt << 8) + wkb + kselB) ^ xmk));

    // Z prefetch for step 0
    float4 zpre0 = *reinterpret_cast<const float4*>(Z + eoff);
    float4 zpre1 = *reinterpret_cast<const float4*>(Z + eoff + 4);

    for (int t = 0; t < T_STEPS; t++) {
        const int cur = t & 1;
        const __nv_bfloat16* h_hi = hhi0 + cur * HS;
        const __nv_bfloat16* h_lo = hlo0 + cur * HS;
        __nv_bfloat16* o_hi = const_cast<__nv_bfloat16*>(hhi0) + (cur ^ 1) * HS;
        __nv_bfloat16* o_lo = const_cast<__nv_bfloat16*>(hlo0) + (cur ^ 1) * HS;

        auto issue = [&](int kt, int buf) {
            const int k0 = kt << 7;
            const uint32_t st = sb + ST_OFF + buf * ST_SZ;
#pragma unroll
            for (int i = 0; i < 4; i++) {           // A_hi: 64 rows x 256B
                const int c = tid + (i << 8);
                const int row = c >> 4, u = c & 15;
                cp_async16(st + row * 256 + ((u * 16) ^ ((row & 7) << 4)),
                           h_hi + (size_t)(m0 + row) * DH + k0 + u * 8);
            }
#pragma unroll
            for (int i = 0; i < 4; i++) {           // A_lo
                const int c = tid + (i << 8);
                const int row = c >> 4, u = c & 15;
                cp_async16(st + 16384 + row * 256 + ((u * 16) ^ ((row & 7) << 4)),
                           h_lo + (size_t)(m0 + row) * DH + k0 + u * 8);
            }
        };

        float acc[4][4][4];
#pragma unroll
        for (int mt = 0; mt < 4; mt++)
#pragma unroll
            for (int n8 = 0; n8 < 4; n8++)
#pragma unroll
                for (int q = 0; q < 4; q++) acc[mt][n8][q] = 0.0f;

        auto compute = [&](int kt, int buf) {
            const uint32_t aHi = sb + ST_OFF + buf * ST_SZ;
            const uint32_t aLo = aHi + 16384;
            const uint32_t tkb = (uint32_t)(kt << 8);
            uint32_t ah[4][4], al[4][4], bl[2][4];
#pragma unroll
            for (int mt = 0; mt < 4; mt++) {
                ldmatrix_x4(ah[mt], aHi + (mt * 16 + rowA) * 256 + ((wkb + kselA) ^ xmk));
                ldmatrix_x4(al[mt], aLo + (mt * 16 + rowA) * 256 + ((wkb + kselA) ^ xmk));
            }
#pragma unroll
            for (int nt = 0; nt < 2; nt++)
                ldmatrix_x4(bl[nt], sb + W_LO_OFF + (nt * 16 + rowBb) * 2048 +
                                        ((tkb + wkb + kselB) ^ xmk));
#pragma unroll
            for (int mt = 0; mt < 4; mt++)
#pragma unroll
                for (int nt = 0; nt < 2; nt++) {
                    mma_bf16(acc[mt][nt * 2],     ah[mt], bhr[kt][nt][0], bhr[kt][nt][1]);
                    mma_bf16(acc[mt][nt * 2 + 1], ah[mt], bhr[kt][nt][2], bhr[kt][nt][3]);
                    mma_bf16(acc[mt][nt * 2],     al[mt], bhr[kt][nt][0], bhr[kt][nt][1]);
                    mma_bf16(acc[mt][nt * 2 + 1], al[mt], bhr[kt][nt][2], bhr[kt][nt][3]);
                    mma_bf16(acc[mt][nt * 2],     ah[mt], bl[nt][0], bl[nt][1]);
                    mma_bf16(acc[mt][nt * 2 + 1], ah[mt], bl[nt][2], bl[nt][3]);
                }
        };

        float* sred = reinterpret_cast<float*>(sm + ST_OFF);

        if (t > 0) {
            issue(0, 0); cp_commit();
            issue(1, 1); cp_commit();

            for (int kt = 0; kt < 8; kt++) {
                cp_wait1();
                __syncthreads();
                if (kt + 2 < 8) issue(kt + 2, (kt + 2) % 3);
                cp_commit();
                compute(kt, kt % 3);
            }

            // ---- cross-warp split-K reduction through smem ----
            cp_wait0();
            __syncthreads();
            float* ms = sred + w * WBP;
            const int g = lane >> 2, t4 = lane & 3;
#pragma unroll
            for (int mt = 0; mt < 4; mt++)
#pragma unroll
                for (int n8 = 0; n8 < 4; n8++) {
                    const int r0 = mt * 16 + g, c = n8 * 8 + 2 * t4;
                    *reinterpret_cast<float2*>(&ms[r0 * RP + c]) =
                        make_float2(acc[mt][n8][0], acc[mt][n8][1]);
                    *reinterpret_cast<float2*>(&ms[(r0 + 8) * RP + c]) =
                        make_float2(acc[mt][n8][2], acc[mt][n8][3]);
                }
            __syncthreads();
        }

        // ---- fused epilogue: sum 8 partials + Z, tanh, store splits ----
#pragma unroll
        for (int q = 0; q < 2; q++) {
            const int col = ec0 + q * 4;
            float4 s = make_float4(0.0f, 0.0f, 0.0f, 0.0f);
            if (t > 0) {
                s = *reinterpret_cast<const float4*>(&sred[erow * RP + col]);
#pragma unroll
                for (int w2 = 1; w2 < 8; w2++) {
                    float4 p = *reinterpret_cast<const float4*>(
                        &sred[w2 * WBP + erow * RP + col]);
                    s.x += p.x; s.y += p.y; s.z += p.z; s.w += p.w;
                }
            }
            const size_t off = eoff + q * 4;
            const float4 z = q ? zpre1 : zpre0;
            float v0 = tanh_fast(s.x + z.x);
            float v1 = tanh_fast(s.y + z.y);
            float v2 = tanh_fast(s.z + z.z);
            float v3 = tanh_fast(s.w + z.w);
            uint32_t u0 = __float_as_uint(v0), u1 = __float_as_uint(v1);
            uint32_t u2 = __float_as_uint(v2), u3 = __float_as_uint(v3);
            *reinterpret_cast<uint2*>(o_hi + off) = make_uint2(prmt_hi(u0, u1), prmt_hi(u2, u3));
            float l0 = v0 - __uint_as_float(u0 & 0xFFFF0000u);
            float l1 = v1 - __uint_as_float(u1 & 0xFFFF0000u);
            float l2 = v2 - __uint_as_float(u2 & 0xFFFF0000u);
            float l3 = v3 - __uint_as_float(u3 & 0xFFFF0000u);
            *reinterpret_cast<uint2*>(o_lo + off) = make_uint2(cvt_bf16x2(l1, l0), cvt_bf16x2(l3, l2));
        }

        // ---- prefetch next step's Z, then per-m-group barrier ----
        if (t < T_STEPS - 1) {
            const float* Zn = Z + (size_t)(t + 1) * HS;
            float4 znx0 = *reinterpret_cast<const float4*>(Zn + eoff);
            float4 znx1 = *reinterpret_cast<const float4*>(Zn + eoff + 4);
            __syncthreads();
            if (tid == 0) {
                int* slot = bar + (t * 4 + mg) * 32;
                asm volatile("red.release.gpu.global.add.s32 [%0], 1;" :: "l"(slot) : "memory");
                int v;
                do {
                    __nanosleep(16);
                    asm volatile("ld.acquire.gpu.global.b32 %0, [%1];" : "=r"(v) : "l"(slot) : "memory");
                } while (v < 32);
            }
            __syncthreads();
            zpre0 = znx0;
            zpre1 = znx1;
        }
    }
}

// =====================================================================
// Generic per-tile 3-term HMMA GEMM (precompute + readout).
// C[M,N] = A[M,K] @ B[N,K]^T (+ bias).  CTA 128(M) x 64(N), 256 thr,
// 8 warps = 4m x 2n, 2-stage 48KB pipeline, occ 2.
// MODE 0: + bias vector aux[n], fp32 C.   MODE 1: + scalar aux[0].
// =====================================================================
#define PST_SZ 49152

template <int KDIM, int NKT, int MODE>
__global__ void __launch_bounds__(256, 2)
gemm3_hmma(const __nv_bfloat16* __restrict__ a_hi, const __nv_bfloat16* __restrict__ a_lo,
           const __nv_bfloat16* __restrict__ b_hi, const __nv_bfloat16* __restrict__ b_lo,
           const float* __restrict__ aux, float* __restrict__ C, int N) {
    extern __shared__ __align__(128) char pool[];   // 2 x 48KB stages

    const int tid = threadIdx.x;
    const int w = tid >> 5;
    const int lane = tid & 31;
    const int mw = w & 3, nw = w >> 2;
    const int n0 = blockIdx.x * 64;
    const int m0 = blockIdx.y * 128;
    const uint32_t base = smem_u32(pool);

    auto issue = [&](int kt, int buf) {
        const int k0 = kt << 6;
        const uint32_t st = base + buf * PST_SZ;
#pragma unroll
        for (int i = 0; i < 4; i++) {               // A_hi: 128 rows x 128B
            const int c = tid + (i << 8);
            const int row = c >> 3, u = c & 7;
            cp_async16(st + row * 128 + ((u * 16) ^ ((row & 7) << 4)),
                       a_hi + (size_t)(m0 + row) * KDIM + k0 + u * 8);
        }
#pragma unroll
        for (int i = 0; i < 4; i++) {               // A_lo
            const int c = tid + (i << 8);
            const int row = c >> 3, u = c & 7;
            cp_async16(st + 16384 + row * 128 + ((u * 16) ^ ((row & 7) << 4)),
                       a_lo + (size_t)(m0 + row) * KDIM + k0 + u * 8);
        }
#pragma unroll
        for (int i = 0; i < 2; i++) {               // B_hi: 64 rows x 128B
            const int c = tid + (i << 8);
            const int row = c >> 3, u = c & 7;
            cp_async16(st + 32768 + row * 128 + ((u * 16) ^ ((row & 7) << 4)),
                       b_hi + (size_t)(n0 + row) * KDIM + k0 + u * 8);
        }
#pragma unroll
        for (int i = 0; i < 2; i++) {               // B_lo
            const int c = tid + (i << 8);
            const int row = c >> 3, u = c & 7;
            cp_async16(st + 40960 + row * 128 + ((u * 16) ^ ((row & 7) << 4)),
                       b_lo + (size_t)(n0 + row) * KDIM + k0 + u * 8);
        }
    };

    const int l7 = lane & 7;
    const uint32_t xmk = (uint32_t)(l7 << 4);
    const int rowA = ((lane >> 3) & 1) * 8 + l7;
    const uint32_t kselA = ((lane >> 4) & 1) * 16;
    const int rowBb = ((lane >> 4) & 1) * 8 + l7;
    const uint32_t kselB = ((lane >> 3) & 1) * 16;

    float acc[2][4][4];
#pragma unroll
    for (int mt = 0; mt < 2; mt++)
#pragma unroll
        for (int n8 = 0; n8 < 4; n8++)
#pragma unroll
            for (int q = 0; q < 4; q++) acc[mt][n8][q] = 0.0f;

    auto compute = [&](int buf) {
        const uint32_t st = base + buf * PST_SZ;
        const uint32_t aHi = st, aLo = st + 16384;
        const uint32_t bHi = st + 32768, bLo = st + 40960;
#pragma unroll
        for (int k16 = 0; k16 < 4; k16++) {
            const uint32_t kb = (uint32_t)(k16 * 32);
            uint32_t ah[2][4], al[2][4];
#pragma unroll
            for (int mt = 0; mt < 2; mt++) {
                ldmatrix_x4(ah[mt], aHi + (mw * 32 + mt * 16 + rowA) * 128 + ((kb + kselA) ^ xmk));
                ldmatrix_x4(al[mt], aLo + (mw * 32 + mt * 16 + rowA) * 128 + ((kb + kselA) ^ xmk));
            }
#pragma unroll
            for (int nt = 0; nt < 2; nt++) {
                uint32_t bh[4], bl[4];
                ldmatrix_x4(bh, bHi + (nw * 32 + nt * 16 + rowBb) * 128 + ((kb + kselB) ^ xmk));
                ldmatrix_x4(bl, bLo + (nw * 32 + nt * 16 + rowBb) * 128 + ((kb + kselB) ^ xmk));
#pragma unroll
                for (int mt = 0; mt < 2; mt++) {
                    mma_bf16(acc[mt][nt * 2],     ah[mt], bh[0], bh[1]);
                    mma_bf16(acc[mt][nt * 2 + 1], ah[mt], bh[2], bh[3]);
                    mma_bf16(acc[mt][nt * 2],     al[mt], bh[0], bh[1]);
                    mma_bf16(acc[mt][nt * 2 + 1], al[mt], bh[2], bh[3]);
                    mma_bf16(acc[mt][nt * 2],     ah[mt], bl[0], bl[1]);
                    mma_bf16(acc[mt][nt * 2 + 1], ah[mt], bl[2], bl[3]);
                }
            }
        }
    };

    issue(0, 0); cp_commit();
    issue(1, 1); cp_commit();
    for (int kt = 0; kt < NKT; kt++) {
        if (kt == NKT - 1) cp_wait0(); else cp_wait1();
        __syncthreads();
        compute(kt & 1);
        if (kt + 2 < NKT) {
            __syncthreads();
            issue(kt + 2, kt & 1);
            cp_commit();
        }
    }

    // epilogue
    const int g = lane >> 2, t4 = lane & 3;
#pragma unroll
    for (int mt = 0; mt < 2; mt++)
#pragma unroll
        for (int n8 = 0; n8 < 4; n8++) {
            const float* c = acc[mt][n8];
            const int col = n0 + nw * 32 + n8 * 8 + 2 * t4;
            const int r0 = m0 + mw * 32 + mt * 16 + g;
            const size_t o0 = (size_t)r0 * N + col;
            const size_t o1 = o0 + 8 * (size_t)N;
            float bx, by;
            if (MODE == 0) {
                float2 bi = *reinterpret_cast<const float2*>(aux + col);
                bx = bi.x; by = bi.y;
            } else {
                bx = by = aux[0];
            }
            *reinterpret_cast<float2*>(C + o0) = make_float2(c[0] + bx, c[1] + by);
            *reinterpret_cast<float2*>(C + o1) = make_float2(c[2] + bx, c[3] + by);
        }
}

// ---------------- host launcher ----------------
extern "C" void kernel_launch(void* const* d_in, const int* in_sizes, int n_in,
                              void* d_out, int out_size) {
    const float* xs  = (const float*)d_in[0];
    const float* W1x = (const float*)d_in[1];
    const float* W1h = (const float*)d_in[2];
    const float* b1  = (const float*)d_in[3];
    const float* W2  = (const float*)d_in[4];
    const float* b2  = (const float*)d_in[5];
    float* out = (float*)d_out;

    float* zp;
    int* barp;
    __nv_bfloat16 *hhi, *hlo, *wthi, *wtlo, *xshi, *xslo, *wxhi, *wxlo, *w2hi, *w2lo;
    cudaGetSymbolAddress((void**)&zp, g_z);
    cudaGetSymbolAddress((void**)&hhi, g_h_hi);
    cudaGetSymbolAddress((void**)&hlo, g_h_lo);
    cudaGetSymbolAddress((void**)&wthi, g_wt_hi);
    cudaGetSymbolAddress((void**)&wtlo, g_wt_lo);
    cudaGetSymbolAddress((void**)&xshi, g_xs_hi);
    cudaGetSymbolAddress((void**)&xslo, g_xs_lo);
    cudaGetSymbolAddress((void**)&wxhi, g_w1xt_hi);
    cudaGetSymbolAddress((void**)&wxlo, g_w1xt_lo);
    cudaGetSymbolAddress((void**)&w2hi, g_w2t_hi);
    cudaGetSymbolAddress((void**)&w2lo, g_w2t_lo);
    cudaGetSymbolAddress((void**)&barp, g_bar);

    cudaFuncSetAttribute(gemm3_hmma<DIN, 4, 0>,
                         cudaFuncAttributeMaxDynamicSharedMemorySize, 2 * PST_SZ);
    cudaFuncSetAttribute(gemm3_hmma<DH, 16, 1>,
                         cudaFuncAttributeMaxDynamicSharedMemorySize, 2 * PST_SZ);
    cudaFuncSetAttribute(rnn_persist, cudaFuncAttributeMaxDynamicSharedMemorySize, SMEM_TOT);

    const int XN = T_STEPS * BATCH * DIN;

    // splits
    fsplit_kernel<<<XN / 4 / 256, 256>>>(xs, xshi, xslo, XN / 4);
    wsplit_kernel<<<dim3(DH / 32, DIN / 32), dim3(32, 8)>>>(W1x, wxhi, wxlo, DIN, DH);
    wsplit_kernel<<<dim3(DH / 32, DH / 32), dim3(32, 8)>>>(W1h, wthi, wtlo, DH, DH);
    wsplit_kernel<<<dim3(DOUT / 32, DH / 32), dim3(32, 8)>>>(W2, w2hi, w2lo, DH, DOUT);

    // zero barrier slots
    zero_u4<<<16, 256>>>((uint4*)barp, T_STEPS * 4 * 32 / 4);

    // Z = xs@W1x + b1 (HMMA, per-tile 3-term)
    gemm3_hmma<DIN, 4, 0><<<dim3(16, 256), 256, 2 * PST_SZ>>>(
        xshi, xslo, wxhi, wxlo, b1, zp, DH);

    // full recurrence in one persistent launch (W resident, per-mg barrier)
    rnn_persist<<<128, 256, SMEM_TOT>>>(hhi, hlo, wthi, wtlo, zp, barp);

    // out = h_final @ W2 + b2  (HMMA, consumes final h splits; final h is in
    // buffer T_STEPS & 1 = 0 ... after 128 steps, last write went to cur^1
    // with cur = 127&1 = 1, so output buffer index 0)
    gemm3_hmma<DH, 16, 1><<<dim3(DOUT / 64, BATCH / 128), 256, 2 * PST_SZ>>>(
        hhi + 0, hlo + 0, w2hi, w2lo, b2, out, DOUT);
}